// round 1
// baseline (speedup 1.0000x reference)
#include <cuda_runtime.h>

// Problem constants
#define THITA 0.0001f
#define NPOS 2304           // 48*48
#define SP 68               // padded tile stride (float4-aligned, low-conflict)
#define WP 65               // padded weight stride (conflict-free transpose)

// Scratch (device globals; no allocations allowed)
__device__ float g_q[4 * 2304 * 64];   // (B, N, C)
__device__ float g_k[4 * 64 * 2304];   // (B, C, N)
__device__ float g_v[4 * 2304 * 64];   // (B, N, C)
__device__ float g_x1[4 * 64 * 2304];  // (B, C, N)

// ---------------------------------------------------------------------------
// 64x64 GEMM + bias + relu on a 64-position tile.
// In  : [c][j]  stride SP (smem)
// Wt  : [c][o]  stride WP (smem, transposed weight)
// Out : [o][j]  stride SP (smem)
// Thread (tx,ty) in 16x16 grid computes o = ty*4..+3, j = tx*4..+3.
// ---------------------------------------------------------------------------
__device__ __forceinline__ void gemm64_relu(
    const float* __restrict__ In,
    const float* __restrict__ Wt,
    const float* __restrict__ bias,
    float* __restrict__ Out,
    int tx, int ty)
{
    float acc[4][4];
#pragma unroll
    for (int i = 0; i < 4; i++)
#pragma unroll
        for (int j = 0; j < 4; j++) acc[i][j] = 0.f;

#pragma unroll 16
    for (int c = 0; c < 64; ++c) {
        float4 xv = *reinterpret_cast<const float4*>(In + c * SP + tx * 4);
        float w0 = Wt[c * WP + ty * 4 + 0];
        float w1 = Wt[c * WP + ty * 4 + 1];
        float w2 = Wt[c * WP + ty * 4 + 2];
        float w3 = Wt[c * WP + ty * 4 + 3];
        acc[0][0] += w0 * xv.x; acc[0][1] += w0 * xv.y; acc[0][2] += w0 * xv.z; acc[0][3] += w0 * xv.w;
        acc[1][0] += w1 * xv.x; acc[1][1] += w1 * xv.y; acc[1][2] += w1 * xv.z; acc[1][3] += w1 * xv.w;
        acc[2][0] += w2 * xv.x; acc[2][1] += w2 * xv.y; acc[2][2] += w2 * xv.z; acc[2][3] += w2 * xv.w;
        acc[3][0] += w3 * xv.x; acc[3][1] += w3 * xv.y; acc[3][2] += w3 * xv.z; acc[3][3] += w3 * xv.w;
    }
#pragma unroll
    for (int i = 0; i < 4; i++) {
        float bb = bias[ty * 4 + i];
        float4 o4;
        o4.x = fmaxf(acc[i][0] + bb, 0.f);
        o4.y = fmaxf(acc[i][1] + bb, 0.f);
        o4.z = fmaxf(acc[i][2] + bb, 0.f);
        o4.w = fmaxf(acc[i][3] + bb, 0.f);
        *reinterpret_cast<float4*>(Out + (ty * 4 + i) * SP + tx * 4) = o4;
    }
}

// Load 64x64 weight [o][c] (global, row-major) into smem transposed [c][o], stride WP.
__device__ __forceinline__ void loadWt(const float* __restrict__ Wg,
                                       float* __restrict__ Wt, int tid)
{
#pragma unroll
    for (int idx = tid; idx < 4096; idx += 256) {
        int o = idx >> 6, c = idx & 63;
        Wt[c * WP + o] = Wg[idx];   // smem bank (c+o)%32: conflict-free; global coalesced
    }
}

// ---------------------------------------------------------------------------
// Projection kernel: per (batch, 64-position tile), compute
//   x1, x2, q, v  (x path)  and  ef0, ef1, k  (event path, subsample FIRST).
// ---------------------------------------------------------------------------
__global__ __launch_bounds__(256, 1)
void proj_kernel(const float* __restrict__ x, const float* __restrict__ event,
                 const float* __restrict__ Wx0, const float* __restrict__ bx0,
                 const float* __restrict__ Wx1, const float* __restrict__ bx1,
                 const float* __restrict__ We0, const float* __restrict__ be0,
                 const float* __restrict__ We1, const float* __restrict__ be1,
                 const float* __restrict__ Wq,  const float* __restrict__ bq,
                 const float* __restrict__ Wk,  const float* __restrict__ bk,
                 const float* __restrict__ Wv,  const float* __restrict__ bv)
{
    extern __shared__ float sm[];
    float* S0 = sm;                 // 64*SP
    float* S1 = S0 + 64 * SP;       // 64*SP
    float* Wt = S1 + 64 * SP;       // 64*WP

    int tid = threadIdx.x;
    int tx = tid & 15, ty = tid >> 4;
    int b = blockIdx.x / 36;
    int n0 = (blockIdx.x % 36) * 64;

    // ---- x path ----
    const float* xb = x + b * 64 * NPOS + n0;
#pragma unroll
    for (int idx = tid; idx < 4096; idx += 256) {
        int c = idx >> 6, j = idx & 63;
        S0[c * SP + j] = xb[c * NPOS + j];
    }
    loadWt(Wx0, Wt, tid);
    __syncthreads();
    gemm64_relu(S0, Wt, bx0, S1, tx, ty);               // S1 = x1
    __syncthreads();

    float* x1b = g_x1 + b * 64 * NPOS + n0;
#pragma unroll
    for (int idx = tid; idx < 4096; idx += 256) {
        int c = idx >> 6, j = idx & 63;
        x1b[c * NPOS + j] = S1[c * SP + j];
    }
    loadWt(Wx1, Wt, tid);
    __syncthreads();
    gemm64_relu(S1, Wt, bx1, S0, tx, ty);               // S0 = x2
    __syncthreads();

    loadWt(Wq, Wt, tid);
    __syncthreads();
    gemm64_relu(S0, Wt, bq, S1, tx, ty);                // S1 = q
    __syncthreads();

    float* qb = g_q + (b * NPOS + n0) * 64;
#pragma unroll
    for (int idx = tid; idx < 4096; idx += 256) {
        int nl = idx >> 6, o = idx & 63;
        qb[nl * 64 + o] = S1[o * SP + nl];              // transposed store (B,N,C)
    }
    loadWt(Wv, Wt, tid);
    __syncthreads();
    gemm64_relu(S0, Wt, bv, S1, tx, ty);                // S1 = v (from x2 still in S0)
    __syncthreads();

    float* vb = g_v + (b * NPOS + n0) * 64;
#pragma unroll
    for (int idx = tid; idx < 4096; idx += 256) {
        int nl = idx >> 6, o = idx & 63;
        vb[nl * 64 + o] = S1[o * SP + nl];
    }

    // ---- event path: subsample ::16 commutes with 1x1 conv ----
    const float* eb = event + (long)b * 64 * 768 * 768;
#pragma unroll
    for (int idx = tid; idx < 4096; idx += 256) {
        int c = idx >> 6, j = idx & 63;
        int n = n0 + j;
        int hh = n / 48;
        int ww = n - hh * 48;
        S0[c * SP + j] = eb[((long)c * 768 + hh * 16) * 768 + ww * 16];
    }
    loadWt(We0, Wt, tid);
    __syncthreads();
    gemm64_relu(S0, Wt, be0, S1, tx, ty);               // ef0
    __syncthreads();
    loadWt(We1, Wt, tid);
    __syncthreads();
    gemm64_relu(S1, Wt, be1, S0, tx, ty);               // ef1
    __syncthreads();
    loadWt(Wk, Wt, tid);
    __syncthreads();
    gemm64_relu(S0, Wt, bk, S1, tx, ty);                // k
    __syncthreads();

    float* kb2 = g_k + b * 64 * NPOS + n0;
#pragma unroll
    for (int idx = tid; idx < 4096; idx += 256) {
        int c = idx >> 6, j = idx & 63;
        kb2[c * NPOS + j] = S1[c * SP + j];             // (B,C,N), coalesced
    }
}

// ---------------------------------------------------------------------------
// Flash-style attention + epilogue: out = THITA*gamma*(softmax(QK^T)V) + x1.
// One CTA = 64 query rows of one batch. 36 key blocks of 64.
// ---------------------------------------------------------------------------
__global__ __launch_bounds__(256, 1)
void attn_kernel(const float* __restrict__ gamma, float* __restrict__ out)
{
    extern __shared__ float sm[];
    float* Qt = sm;                  // [d][r]  stride 68
    float* Kt = Qt + 64 * 68;        // [d][k]  stride 64
    float* Vs = Kt + 64 * 64;        // [n][d]  stride 64
    float* Pt = Vs + 64 * 64;        // [n][r]  stride 68 ; reused as Os (stride 65)

    int tid = threadIdx.x;
    int tx = tid & 15, ty = tid >> 4;
    int b = blockIdx.x / 36;
    int m0 = (blockIdx.x % 36) * 64;

    const float* qg = g_q + (b * NPOS + m0) * 64;
#pragma unroll
    for (int idx = tid; idx < 4096; idx += 256) {
        int r = idx >> 6, d = idx & 63;
        Qt[d * 68 + r] = qg[idx];
    }

    float mI[4], lI[4], O[4][4];
#pragma unroll
    for (int i = 0; i < 4; i++) {
        mI[i] = -1e30f; lI[i] = 0.f;
#pragma unroll
        for (int j = 0; j < 4; j++) O[i][j] = 0.f;
    }

    const float* kgb = g_k + b * 64 * NPOS;
    const float* vgb = g_v + b * NPOS * 64;

    for (int kb = 0; kb < 36; ++kb) {
        int n0 = kb * 64;
        __syncthreads();   // prior PV reads of Kt/Vs/Pt complete
#pragma unroll
        for (int idx = tid; idx < 4096; idx += 256) {
            int d = idx >> 6, k = idx & 63;
            Kt[idx] = kgb[d * NPOS + n0 + k];
        }
#pragma unroll
        for (int idx = tid; idx < 4096; idx += 256) {
            Vs[idx] = vgb[n0 * 64 + idx];
        }
        __syncthreads();

        // S = Q K^T for this block
        float s[4][4];
#pragma unroll
        for (int i = 0; i < 4; i++)
#pragma unroll
            for (int j = 0; j < 4; j++) s[i][j] = 0.f;
#pragma unroll 16
        for (int d = 0; d < 64; ++d) {
            float4 qv = *reinterpret_cast<const float4*>(Qt + d * 68 + ty * 4);
            float4 kv = *reinterpret_cast<const float4*>(Kt + d * 64 + tx * 4);
            s[0][0] += qv.x * kv.x; s[0][1] += qv.x * kv.y; s[0][2] += qv.x * kv.z; s[0][3] += qv.x * kv.w;
            s[1][0] += qv.y * kv.x; s[1][1] += qv.y * kv.y; s[1][2] += qv.y * kv.z; s[1][3] += qv.y * kv.w;
            s[2][0] += qv.z * kv.x; s[2][1] += qv.z * kv.y; s[2][2] += qv.z * kv.z; s[2][3] += qv.z * kv.w;
            s[3][0] += qv.w * kv.x; s[3][1] += qv.w * kv.y; s[3][2] += qv.w * kv.z; s[3][3] += qv.w * kv.w;
        }

        // online softmax (row r owned by 16 lanes in same half-warp)
#pragma unroll
        for (int i = 0; i < 4; i++) {
            float rmax = fmaxf(fmaxf(s[i][0], s[i][1]), fmaxf(s[i][2], s[i][3]));
#pragma unroll
            for (int off = 8; off >= 1; off >>= 1)
                rmax = fmaxf(rmax, __shfl_xor_sync(0xffffffffu, rmax, off));
            float mnew = fmaxf(mI[i], rmax);
            float corr = __expf(mI[i] - mnew);
            float rsum = 0.f;
#pragma unroll
            for (int j = 0; j < 4; j++) {
                float p = __expf(s[i][j] - mnew);
                s[i][j] = p;
                rsum += p;
            }
#pragma unroll
            for (int off = 8; off >= 1; off >>= 1)
                rsum += __shfl_xor_sync(0xffffffffu, rsum, off);
            lI[i] = lI[i] * corr + rsum;
            mI[i] = mnew;
#pragma unroll
            for (int j = 0; j < 4; j++) O[i][j] *= corr;
        }

        // P -> smem transposed [key][row], float4 over rows
#pragma unroll
        for (int j = 0; j < 4; j++) {
            float4 pv = make_float4(s[0][j], s[1][j], s[2][j], s[3][j]);
            *reinterpret_cast<float4*>(Pt + (tx * 4 + j) * 68 + ty * 4) = pv;
        }
        __syncthreads();

        // O += P V
#pragma unroll 16
        for (int n = 0; n < 64; ++n) {
            float4 pv = *reinterpret_cast<const float4*>(Pt + n * 68 + ty * 4);
            float4 vv = *reinterpret_cast<const float4*>(Vs + n * 64 + tx * 4);
            O[0][0] += pv.x * vv.x; O[0][1] += pv.x * vv.y; O[0][2] += pv.x * vv.z; O[0][3] += pv.x * vv.w;
            O[1][0] += pv.y * vv.x; O[1][1] += pv.y * vv.y; O[1][2] += pv.y * vv.z; O[1][3] += pv.y * vv.w;
            O[2][0] += pv.z * vv.x; O[2][1] += pv.z * vv.y; O[2][2] += pv.z * vv.z; O[2][3] += pv.z * vv.w;
            O[3][0] += pv.w * vv.x; O[3][1] += pv.w * vv.y; O[3][2] += pv.w * vv.z; O[3][3] += pv.w * vv.w;
        }
    }
    __syncthreads();

    // epilogue: normalize, scale, add x1, write (B,C,H,W)
    float g = THITA * gamma[0];
    float* Os = Pt;   // reuse, stride 65 (conflict-free column reads)
#pragma unroll
    for (int i = 0; i < 4; i++) {
        float inv = 1.f / lI[i];
#pragma unroll
        for (int j = 0; j < 4; j++)
            Os[(ty * 4 + i) * 65 + tx * 4 + j] = O[i][j] * inv;
    }
    __syncthreads();

    const float* x1b = g_x1 + b * 64 * NPOS + m0;
    float* ob = out + b * 64 * NPOS + m0;
#pragma unroll
    for (int idx = tid; idx < 4096; idx += 256) {
        int c = idx >> 6, m = idx & 63;
        ob[c * NPOS + m] = g * Os[m * 65 + c] + x1b[c * NPOS + m];
    }
}

// ---------------------------------------------------------------------------
extern "C" void kernel_launch(void* const* d_in, const int* in_sizes, int n_in,
                              void* d_out, int out_size)
{
    const float* x     = (const float*)d_in[0];
    const float* event = (const float*)d_in[1];
    const float* Wx0 = (const float*)d_in[2];
    const float* bx0 = (const float*)d_in[3];
    const float* Wx1 = (const float*)d_in[4];
    const float* bx1 = (const float*)d_in[5];
    const float* We0 = (const float*)d_in[6];
    const float* be0 = (const float*)d_in[7];
    const float* We1 = (const float*)d_in[8];
    const float* be1 = (const float*)d_in[9];
    const float* Wq  = (const float*)d_in[10];
    const float* bq  = (const float*)d_in[11];
    const float* Wk  = (const float*)d_in[12];
    const float* bk  = (const float*)d_in[13];
    const float* Wv  = (const float*)d_in[14];
    const float* bv  = (const float*)d_in[15];
    const float* gamma = (const float*)d_in[16];
    float* out = (float*)d_out;

    const int proj_smem = (2 * 64 * SP + 64 * WP) * (int)sizeof(float);   // 51456 B
    const int attn_smem = (64 * 68 + 64 * 64 + 64 * 64 + 64 * 68) * (int)sizeof(float); // 67584 B

    cudaFuncSetAttribute(proj_kernel, cudaFuncAttributeMaxDynamicSharedMemorySize, proj_smem);
    cudaFuncSetAttribute(attn_kernel, cudaFuncAttributeMaxDynamicSharedMemorySize, attn_smem);

    proj_kernel<<<144, 256, proj_smem>>>(x, event,
                                         Wx0, bx0, Wx1, bx1,
                                         We0, be0, We1, be1,
                                         Wq, bq, Wk, bk, Wv, bv);
    attn_kernel<<<144, 256, attn_smem>>>(gamma, out);
}

// round 4
// speedup vs baseline: 3.5412x; 3.5412x over previous
#include <cuda_runtime.h>
#include <cuda_bf16.h>
#include <cstdint>

#define THITA 0.0001f
#define NPOS 2304
#define SP 68
#define WP 65
#define EXP_SHIFT 16.0f

// Scratch (device globals) — 16B+ alignment required for cp.async/uint4
__device__ __align__(128) __nv_bfloat16 g_qb[4 * 2304 * 64];  // (B, N, C)
__device__ __align__(128) __nv_bfloat16 g_kb[4 * 2304 * 64];  // (B, N, C)
__device__ __align__(128) __nv_bfloat16 g_vb[4 * 64 * 2304];  // (B, C, N)
__device__ __align__(128) float         g_x1[4 * 64 * 2304];  // (B, C, N)

// ===========================================================================
// Generic-PTX helpers (valid on compute_103 target: no tcgen05)
// ===========================================================================
__device__ __forceinline__ uint32_t smem_u32(const void* p) {
    uint32_t a;
    asm("{ .reg .u64 t; cvta.to.shared.u64 t, %1; cvt.u32.u64 %0, t; }" : "=r"(a) : "l"(p));
    return a;
}

#define CP16(dst, src) asm volatile("cp.async.cg.shared.global [%0], [%1], 16;" :: "r"(dst), "l"(src))
#define CP_COMMIT()    asm volatile("cp.async.commit_group;" ::: "memory")
#define CP_WAIT0()     asm volatile("cp.async.wait_group 0;" ::: "memory")

__device__ __forceinline__ void ldsm4(uint32_t* r, uint32_t addr) {
    asm volatile("ldmatrix.sync.aligned.m8n8.x4.shared.b16 {%0,%1,%2,%3}, [%4];"
                 : "=r"(r[0]), "=r"(r[1]), "=r"(r[2]), "=r"(r[3]) : "r"(addr));
}

__device__ __forceinline__ void mma16816(float* c, const uint32_t* a,
                                         uint32_t b0, uint32_t b1) {
    asm volatile("mma.sync.aligned.m16n8k16.row.col.f32.bf16.bf16.f32 "
                 "{%0,%1,%2,%3}, {%4,%5,%6,%7}, {%8,%9}, {%0,%1,%2,%3};"
                 : "+f"(c[0]), "+f"(c[1]), "+f"(c[2]), "+f"(c[3])
                 : "r"(a[0]), "r"(a[1]), "r"(a[2]), "r"(a[3]), "r"(b0), "r"(b1));
}

__device__ __forceinline__ uint32_t pack_bf16x2(float lo, float hi) {
    uint32_t r;
    asm("cvt.rn.bf16x2.f32 %0, %1, %2;" : "=r"(r) : "f"(hi), "f"(lo));
    return r;
}

// ===========================================================================
// Projection kernel (q/k -> (B,N,C) bf16, v -> (B,C,N) bf16, x1 fp32)
// ===========================================================================
__device__ __forceinline__ void gemm64_relu(
    const float* __restrict__ In, const float* __restrict__ Wt,
    const float* __restrict__ bias, float* __restrict__ Out, int tx, int ty)
{
    float acc[4][4];
#pragma unroll
    for (int i = 0; i < 4; i++)
#pragma unroll
        for (int j = 0; j < 4; j++) acc[i][j] = 0.f;
#pragma unroll 16
    for (int c = 0; c < 64; ++c) {
        float4 xv = *reinterpret_cast<const float4*>(In + c * SP + tx * 4);
        float w0 = Wt[c * WP + ty * 4 + 0];
        float w1 = Wt[c * WP + ty * 4 + 1];
        float w2 = Wt[c * WP + ty * 4 + 2];
        float w3 = Wt[c * WP + ty * 4 + 3];
        acc[0][0] += w0 * xv.x; acc[0][1] += w0 * xv.y; acc[0][2] += w0 * xv.z; acc[0][3] += w0 * xv.w;
        acc[1][0] += w1 * xv.x; acc[1][1] += w1 * xv.y; acc[1][2] += w1 * xv.z; acc[1][3] += w1 * xv.w;
        acc[2][0] += w2 * xv.x; acc[2][1] += w2 * xv.y; acc[2][2] += w2 * xv.z; acc[2][3] += w2 * xv.w;
        acc[3][0] += w3 * xv.x; acc[3][1] += w3 * xv.y; acc[3][2] += w3 * xv.z; acc[3][3] += w3 * xv.w;
    }
#pragma unroll
    for (int i = 0; i < 4; i++) {
        float bb = bias[ty * 4 + i];
        float4 o4;
        o4.x = fmaxf(acc[i][0] + bb, 0.f);
        o4.y = fmaxf(acc[i][1] + bb, 0.f);
        o4.z = fmaxf(acc[i][2] + bb, 0.f);
        o4.w = fmaxf(acc[i][3] + bb, 0.f);
        *reinterpret_cast<float4*>(Out + (ty * 4 + i) * SP + tx * 4) = o4;
    }
}

__device__ __forceinline__ void loadWt(const float* __restrict__ Wg,
                                       float* __restrict__ Wt, int tid)
{
#pragma unroll
    for (int idx = tid; idx < 4096; idx += 256) {
        int o = idx >> 6, c = idx & 63;
        Wt[c * WP + o] = Wg[idx];
    }
}

__global__ __launch_bounds__(256, 1)
void proj_kernel(const float* __restrict__ x, const float* __restrict__ event,
                 const float* __restrict__ Wx0, const float* __restrict__ bx0,
                 const float* __restrict__ Wx1, const float* __restrict__ bx1,
                 const float* __restrict__ We0, const float* __restrict__ be0,
                 const float* __restrict__ We1, const float* __restrict__ be1,
                 const float* __restrict__ Wq,  const float* __restrict__ bq,
                 const float* __restrict__ Wk,  const float* __restrict__ bk,
                 const float* __restrict__ Wv,  const float* __restrict__ bv)
{
    extern __shared__ float sm[];
    float* S0 = sm;
    float* S1 = S0 + 64 * SP;
    float* Wt = S1 + 64 * SP;

    int tid = threadIdx.x;
    int tx = tid & 15, ty = tid >> 4;
    int b = blockIdx.x / 36;
    int n0 = (blockIdx.x % 36) * 64;

    // ---- x path ----
    const float* xb = x + b * 64 * NPOS + n0;
#pragma unroll
    for (int idx = tid; idx < 4096; idx += 256) {
        int c = idx >> 6, j = idx & 63;
        S0[c * SP + j] = xb[c * NPOS + j];
    }
    loadWt(Wx0, Wt, tid);
    __syncthreads();
    gemm64_relu(S0, Wt, bx0, S1, tx, ty);               // x1
    __syncthreads();

    float* x1b = g_x1 + b * 64 * NPOS + n0;
#pragma unroll
    for (int idx = tid; idx < 4096; idx += 256) {
        int c = idx >> 6, j = idx & 63;
        x1b[c * NPOS + j] = S1[c * SP + j];
    }
    loadWt(Wx1, Wt, tid);
    __syncthreads();
    gemm64_relu(S1, Wt, bx1, S0, tx, ty);               // x2
    __syncthreads();

    loadWt(Wq, Wt, tid);
    __syncthreads();
    gemm64_relu(S0, Wt, bq, S1, tx, ty);                // q
    __syncthreads();

    __nv_bfloat16* qb = g_qb + (size_t)(b * NPOS + n0) * 64;
#pragma unroll
    for (int idx = tid; idx < 4096; idx += 256) {
        int nl = idx >> 6, o = idx & 63;
        qb[nl * 64 + o] = __float2bfloat16(S1[o * SP + nl]);
    }
    loadWt(Wv, Wt, tid);
    __syncthreads();
    gemm64_relu(S0, Wt, bv, S1, tx, ty);                // v
    __syncthreads();

    __nv_bfloat16* vb = g_vb + (size_t)b * 64 * NPOS + n0;
#pragma unroll
    for (int idx = tid; idx < 4096; idx += 256) {
        int c = idx >> 6, j = idx & 63;
        vb[(size_t)c * NPOS + j] = __float2bfloat16(S1[c * SP + j]);
    }

    // ---- event path (subsample commutes with 1x1 conv) ----
    const float* eb = event + (long)b * 64 * 768 * 768;
#pragma unroll
    for (int idx = tid; idx < 4096; idx += 256) {
        int c = idx >> 6, j = idx & 63;
        int n = n0 + j;
        int hh = n / 48;
        int ww = n - hh * 48;
        S0[c * SP + j] = eb[((long)c * 768 + hh * 16) * 768 + ww * 16];
    }
    loadWt(We0, Wt, tid);
    __syncthreads();
    gemm64_relu(S0, Wt, be0, S1, tx, ty);               // ef0
    __syncthreads();
    loadWt(We1, Wt, tid);
    __syncthreads();
    gemm64_relu(S1, Wt, be1, S0, tx, ty);               // ef1
    __syncthreads();
    loadWt(Wk, Wt, tid);
    __syncthreads();
    gemm64_relu(S0, Wt, bk, S1, tx, ty);                // k
    __syncthreads();

    __nv_bfloat16* kb2 = g_kb + (size_t)(b * NPOS + n0) * 64;
#pragma unroll
    for (int idx = tid; idx < 4096; idx += 256) {
        int nl = idx >> 6, o = idx & 63;
        kb2[nl * 64 + o] = __float2bfloat16(S1[o * SP + nl]);
    }
}

// ===========================================================================
// mma.sync attention (FA2-style, no rescale): CTA = 64 query rows of 1 batch,
// 4 warps x 16 rows. 36 key blocks of 64. P = exp(S-16) stays in registers.
// SMEM rows padded to 72 bf16 (144B): conflict-free ldmatrix.
// ===========================================================================
#define TSTRIDE 144          // bytes per smem tile row (72 bf16)
#define SM_Q   0             // 64*144 = 9216
#define SM_K0  9216
#define SM_K1  18432
#define SM_V0  27648
#define SM_V1  36864
#define SM_O   9216          // fp32 64x68 epilogue (17408B) aliases K0/K1
#define ATTN_SMEM 46080

__global__ __launch_bounds__(128, 1)
void attn_mma_kernel(const float* __restrict__ gamma, float* __restrict__ out)
{
    extern __shared__ char smc[];
    const uint32_t sb = smem_u32(smc);
    const int tid = threadIdx.x;
    const int lane = tid & 31, w = tid >> 5;
    const int b = blockIdx.x / 36;
    const int m0 = (blockIdx.x % 36) * 64;

    const char* qg = (const char*)(g_qb + (size_t)(b * NPOS + m0) * 64);
    const char* kg = (const char*)(g_kb + (size_t)b * NPOS * 64);
    const char* vg = (const char*)(g_vb + (size_t)b * 64 * NPOS);

    // prologue: cp.async Q + K0 + V0 (rows are 128B contiguous in global)
#pragma unroll
    for (int it = 0; it < 4; ++it) {
        int idx = tid + it * 128;
        int row = idx >> 3, c16 = (idx & 7) * 16;
        CP16(sb + SM_Q  + row * TSTRIDE + c16, qg + row * 128 + c16);
        CP16(sb + SM_K0 + row * TSTRIDE + c16, kg + row * 128 + c16);
        CP16(sb + SM_V0 + row * TSTRIDE + c16, vg + (size_t)row * (NPOS * 2) + c16);
    }
    CP_COMMIT();
    CP_WAIT0();
    __syncthreads();

    // Q a-fragments (persistent): warp rows w*16..+15
    uint32_t qf[4][4];
    {
        uint32_t base = sb + SM_Q + (w * 16 + (lane & 15)) * TSTRIDE + ((lane >> 4) << 3) * 2;
#pragma unroll
        for (int ks = 0; ks < 4; ++ks) ldsm4(qf[ks], base + ks * 32);
    }

    float O[8][4];
#pragma unroll
    for (int j = 0; j < 8; ++j)
#pragma unroll
        for (int e = 0; e < 4; ++e) O[j][e] = 0.f;
    float lsum0 = 0.f, lsum1 = 0.f;

    const uint32_t koff[2] = { SM_K0, SM_K1 };
    const uint32_t voff[2] = { SM_V0, SM_V1 };
    // ldmatrix x4 address pattern (shared by K and V tiles)
    const int bro = ((lane & 16) >> 1) + (lane & 7);  // row within 16-row pair block
    const int bco = (lane & 8) * 2;                   // byte col offset (0 or 16)

    for (int i = 0; i < 36; ++i) {
        const int buf = i & 1;
        if (i < 35) {
            const int n1 = (i + 1) * 64;
            const char* kgs = kg + (size_t)n1 * 128;
#pragma unroll
            for (int it = 0; it < 4; ++it) {
                int idx = tid + it * 128;
                int row = idx >> 3, c16 = (idx & 7) * 16;
                CP16(sb + koff[buf ^ 1] + row * TSTRIDE + c16, kgs + row * 128 + c16);
                CP16(sb + voff[buf ^ 1] + row * TSTRIDE + c16,
                     vg + (size_t)row * (NPOS * 2) + n1 * 2 + c16);
            }
            CP_COMMIT();
        }

        // S = Q K^T  (8 n-tiles of 8 keys)
        float S[8][4];
#pragma unroll
        for (int j = 0; j < 8; ++j)
#pragma unroll
            for (int e = 0; e < 4; ++e) S[j][e] = 0.f;
#pragma unroll
        for (int ks = 0; ks < 4; ++ks) {
#pragma unroll
            for (int p = 0; p < 4; ++p) {
                uint32_t kb[4];
                ldsm4(kb, sb + koff[buf] + (16 * p + bro) * TSTRIDE + ks * 32 + bco);
                mma16816(S[2 * p],     qf[ks], kb[0], kb[1]);
                mma16816(S[2 * p + 1], qf[ks], kb[2], kb[3]);
            }
        }

        // P = exp(S - 16), accumulate row sums, repack c-frag -> a-frag (bf16)
        uint32_t P[4][4];
#pragma unroll
        for (int j = 0; j < 8; ++j) {
            float e0 = __expf(S[j][0] - EXP_SHIFT);
            float e1 = __expf(S[j][1] - EXP_SHIFT);
            float e2 = __expf(S[j][2] - EXP_SHIFT);
            float e3 = __expf(S[j][3] - EXP_SHIFT);
            lsum0 += e0 + e1;
            lsum1 += e2 + e3;
            P[j >> 1][(j & 1) * 2 + 0] = pack_bf16x2(e0, e1);
            P[j >> 1][(j & 1) * 2 + 1] = pack_bf16x2(e2, e3);
        }

        // O += P V  (8 channel-tiles)
#pragma unroll
        for (int ks = 0; ks < 4; ++ks) {
#pragma unroll
            for (int p = 0; p < 4; ++p) {
                uint32_t vb[4];
                ldsm4(vb, sb + voff[buf] + (16 * p + bro) * TSTRIDE + ks * 32 + bco);
                mma16816(O[2 * p],     P[ks], vb[0], vb[1]);
                mma16816(O[2 * p + 1], P[ks], vb[2], vb[3]);
            }
        }

        if (i < 35) CP_WAIT0();
        __syncthreads();
    }

    // finalize row sums across the 4 lanes sharing each row
    lsum0 += __shfl_xor_sync(0xffffffffu, lsum0, 1);
    lsum0 += __shfl_xor_sync(0xffffffffu, lsum0, 2);
    lsum1 += __shfl_xor_sync(0xffffffffu, lsum1, 1);
    lsum1 += __shfl_xor_sync(0xffffffffu, lsum1, 2);
    const float gm = THITA * gamma[0];
    const float inv0 = gm / lsum0;
    const float inv1 = gm / lsum1;

    // epilogue: frags -> smem (c, m) fp32, stride 68 (conflict-free)
    float* so = (float*)(smc + SM_O);
    {
        int g = lane >> 2, t2 = (lane & 3) * 2;
        int m_lo = w * 16 + g, m_hi = m_lo + 8;
#pragma unroll
        for (int j = 0; j < 8; ++j) {
            int c = 8 * j + t2;
            so[c * 68 + m_lo]       = O[j][0] * inv0;
            so[(c + 1) * 68 + m_lo] = O[j][1] * inv0;
            so[c * 68 + m_hi]       = O[j][2] * inv1;
            so[(c + 1) * 68 + m_hi] = O[j][3] * inv1;
        }
    }
    __syncthreads();

    // out[c][m] = so[c][m] + x1[c][m]  (coalesced float4)
    const float* x1b = g_x1 + (size_t)b * 64 * NPOS + m0;
    float* ob = out + (size_t)b * 64 * NPOS + m0;
#pragma unroll
    for (int it = 0; it < 8; ++it) {
        int idx = tid + it * 128;            // 0..1023
        int c = idx >> 4, m4 = (idx & 15) * 4;
        float4 o4 = *(const float4*)(so + c * 68 + m4);
        float4 xv = *(const float4*)(x1b + (size_t)c * NPOS + m4);
        float4 r;
        r.x = o4.x + xv.x; r.y = o4.y + xv.y;
        r.z = o4.z + xv.z; r.w = o4.w + xv.w;
        *(float4*)(ob + (size_t)c * NPOS + m4) = r;
    }
}

// ===========================================================================
extern "C" void kernel_launch(void* const* d_in, const int* in_sizes, int n_in,
                              void* d_out, int out_size)
{
    const float* x     = (const float*)d_in[0];
    const float* event = (const float*)d_in[1];
    const float* Wx0 = (const float*)d_in[2];
    const float* bx0 = (const float*)d_in[3];
    const float* Wx1 = (const float*)d_in[4];
    const float* bx1 = (const float*)d_in[5];
    const float* We0 = (const float*)d_in[6];
    const float* be0 = (const float*)d_in[7];
    const float* We1 = (const float*)d_in[8];
    const float* be1 = (const float*)d_in[9];
    const float* Wq  = (const float*)d_in[10];
    const float* bq  = (const float*)d_in[11];
    const float* Wk  = (const float*)d_in[12];
    const float* bk  = (const float*)d_in[13];
    const float* Wv  = (const float*)d_in[14];
    const float* bv  = (const float*)d_in[15];
    const float* gamma = (const float*)d_in[16];
    float* out = (float*)d_out;

    const int proj_smem = (2 * 64 * SP + 64 * WP) * (int)sizeof(float);

    cudaFuncSetAttribute(proj_kernel, cudaFuncAttributeMaxDynamicSharedMemorySize, proj_smem);
    cudaFuncSetAttribute(attn_mma_kernel, cudaFuncAttributeMaxDynamicSharedMemorySize, ATTN_SMEM);

    proj_kernel<<<144, 256, proj_smem>>>(x, event,
                                         Wx0, bx0, Wx1, bx1,
                                         We0, be0, We1, be1,
                                         Wq, bq, Wk, bk, Wv, bv);
    attn_mma_kernel<<<144, 128, ATTN_SMEM>>>(gamma, out);
}

// round 5
// speedup vs baseline: 3.6660x; 1.0353x over previous
#include <cuda_runtime.h>
#include <cuda_bf16.h>
#include <cstdint>

#define THITA 0.0001f
#define NPOS 2304
#define SP 68
#define WP 65
#define EXP_SHIFT 16.0f

// Scratch (device globals)
__device__ __align__(128) __nv_bfloat16 g_qb[4 * 2304 * 64];  // (B, N, C)
__device__ __align__(128) __nv_bfloat16 g_kb[4 * 2304 * 64];  // (B, N, C)
__device__ __align__(128) __nv_bfloat16 g_vb[4 * 64 * 2304];  // (B, C, N)
__device__ __align__(128) float         g_x1[4 * 64 * 2304];  // (B, C, N)

// ===========================================================================
// Generic-PTX helpers (compute_103-safe: no tcgen05)
// ===========================================================================
__device__ __forceinline__ uint32_t smem_u32(const void* p) {
    uint32_t a;
    asm("{ .reg .u64 t; cvta.to.shared.u64 t, %1; cvt.u32.u64 %0, t; }" : "=r"(a) : "l"(p));
    return a;
}

#define CP16(dst, src) asm volatile("cp.async.cg.shared.global [%0], [%1], 16;" :: "r"(dst), "l"(src))
#define CP_COMMIT()    asm volatile("cp.async.commit_group;" ::: "memory")
#define CP_WAIT0()     asm volatile("cp.async.wait_group 0;" ::: "memory")

__device__ __forceinline__ void ldsm4(uint32_t* r, uint32_t addr) {
    asm volatile("ldmatrix.sync.aligned.m8n8.x4.shared.b16 {%0,%1,%2,%3}, [%4];"
                 : "=r"(r[0]), "=r"(r[1]), "=r"(r[2]), "=r"(r[3]) : "r"(addr));
}

__device__ __forceinline__ void mma16816(float* c, const uint32_t* a,
                                         uint32_t b0, uint32_t b1) {
    asm volatile("mma.sync.aligned.m16n8k16.row.col.f32.bf16.bf16.f32 "
                 "{%0,%1,%2,%3}, {%4,%5,%6,%7}, {%8,%9}, {%0,%1,%2,%3};"
                 : "+f"(c[0]), "+f"(c[1]), "+f"(c[2]), "+f"(c[3])
                 : "r"(a[0]), "r"(a[1]), "r"(a[2]), "r"(a[3]), "r"(b0), "r"(b1));
}

__device__ __forceinline__ uint32_t pack_bf16x2(float lo, float hi) {
    uint32_t r;
    asm("cvt.rn.bf16x2.f32 %0, %1, %2;" : "=r"(r) : "f"(hi), "f"(lo));
    return r;
}

// ===========================================================================
// Projection kernel (unchanged)
// ===========================================================================
__device__ __forceinline__ void gemm64_relu(
    const float* __restrict__ In, const float* __restrict__ Wt,
    const float* __restrict__ bias, float* __restrict__ Out, int tx, int ty)
{
    float acc[4][4];
#pragma unroll
    for (int i = 0; i < 4; i++)
#pragma unroll
        for (int j = 0; j < 4; j++) acc[i][j] = 0.f;
#pragma unroll 16
    for (int c = 0; c < 64; ++c) {
        float4 xv = *reinterpret_cast<const float4*>(In + c * SP + tx * 4);
        float w0 = Wt[c * WP + ty * 4 + 0];
        float w1 = Wt[c * WP + ty * 4 + 1];
        float w2 = Wt[c * WP + ty * 4 + 2];
        float w3 = Wt[c * WP + ty * 4 + 3];
        acc[0][0] += w0 * xv.x; acc[0][1] += w0 * xv.y; acc[0][2] += w0 * xv.z; acc[0][3] += w0 * xv.w;
        acc[1][0] += w1 * xv.x; acc[1][1] += w1 * xv.y; acc[1][2] += w1 * xv.z; acc[1][3] += w1 * xv.w;
        acc[2][0] += w2 * xv.x; acc[2][1] += w2 * xv.y; acc[2][2] += w2 * xv.z; acc[2][3] += w2 * xv.w;
        acc[3][0] += w3 * xv.x; acc[3][1] += w3 * xv.y; acc[3][2] += w3 * xv.z; acc[3][3] += w3 * xv.w;
    }
#pragma unroll
    for (int i = 0; i < 4; i++) {
        float bb = bias[ty * 4 + i];
        float4 o4;
        o4.x = fmaxf(acc[i][0] + bb, 0.f);
        o4.y = fmaxf(acc[i][1] + bb, 0.f);
        o4.z = fmaxf(acc[i][2] + bb, 0.f);
        o4.w = fmaxf(acc[i][3] + bb, 0.f);
        *reinterpret_cast<float4*>(Out + (ty * 4 + i) * SP + tx * 4) = o4;
    }
}

__device__ __forceinline__ void loadWt(const float* __restrict__ Wg,
                                       float* __restrict__ Wt, int tid)
{
#pragma unroll
    for (int idx = tid; idx < 4096; idx += 256) {
        int o = idx >> 6, c = idx & 63;
        Wt[c * WP + o] = Wg[idx];
    }
}

__global__ __launch_bounds__(256, 1)
void proj_kernel(const float* __restrict__ x, const float* __restrict__ event,
                 const float* __restrict__ Wx0, const float* __restrict__ bx0,
                 const float* __restrict__ Wx1, const float* __restrict__ bx1,
                 const float* __restrict__ We0, const float* __restrict__ be0,
                 const float* __restrict__ We1, const float* __restrict__ be1,
                 const float* __restrict__ Wq,  const float* __restrict__ bq,
                 const float* __restrict__ Wk,  const float* __restrict__ bk,
                 const float* __restrict__ Wv,  const float* __restrict__ bv)
{
    extern __shared__ float sm[];
    float* S0 = sm;
    float* S1 = S0 + 64 * SP;
    float* Wt = S1 + 64 * SP;

    int tid = threadIdx.x;
    int tx = tid & 15, ty = tid >> 4;
    int b = blockIdx.x / 36;
    int n0 = (blockIdx.x % 36) * 64;

    const float* xb = x + b * 64 * NPOS + n0;
#pragma unroll
    for (int idx = tid; idx < 4096; idx += 256) {
        int c = idx >> 6, j = idx & 63;
        S0[c * SP + j] = xb[c * NPOS + j];
    }
    loadWt(Wx0, Wt, tid);
    __syncthreads();
    gemm64_relu(S0, Wt, bx0, S1, tx, ty);               // x1
    __syncthreads();

    float* x1b = g_x1 + b * 64 * NPOS + n0;
#pragma unroll
    for (int idx = tid; idx < 4096; idx += 256) {
        int c = idx >> 6, j = idx & 63;
        x1b[c * NPOS + j] = S1[c * SP + j];
    }
    loadWt(Wx1, Wt, tid);
    __syncthreads();
    gemm64_relu(S1, Wt, bx1, S0, tx, ty);               // x2
    __syncthreads();

    loadWt(Wq, Wt, tid);
    __syncthreads();
    gemm64_relu(S0, Wt, bq, S1, tx, ty);                // q
    __syncthreads();

    __nv_bfloat16* qb = g_qb + (size_t)(b * NPOS + n0) * 64;
#pragma unroll
    for (int idx = tid; idx < 4096; idx += 256) {
        int nl = idx >> 6, o = idx & 63;
        qb[nl * 64 + o] = __float2bfloat16(S1[o * SP + nl]);
    }
    loadWt(Wv, Wt, tid);
    __syncthreads();
    gemm64_relu(S0, Wt, bv, S1, tx, ty);                // v
    __syncthreads();

    __nv_bfloat16* vb = g_vb + (size_t)b * 64 * NPOS + n0;
#pragma unroll
    for (int idx = tid; idx < 4096; idx += 256) {
        int c = idx >> 6, j = idx & 63;
        vb[(size_t)c * NPOS + j] = __float2bfloat16(S1[c * SP + j]);
    }

    const float* eb = event + (long)b * 64 * 768 * 768;
#pragma unroll
    for (int idx = tid; idx < 4096; idx += 256) {
        int c = idx >> 6, j = idx & 63;
        int n = n0 + j;
        int hh = n / 48;
        int ww = n - hh * 48;
        S0[c * SP + j] = eb[((long)c * 768 + hh * 16) * 768 + ww * 16];
    }
    loadWt(We0, Wt, tid);
    __syncthreads();
    gemm64_relu(S0, Wt, be0, S1, tx, ty);               // ef0
    __syncthreads();
    loadWt(We1, Wt, tid);
    __syncthreads();
    gemm64_relu(S1, Wt, be1, S0, tx, ty);               // ef1
    __syncthreads();
    loadWt(Wk, Wt, tid);
    __syncthreads();
    gemm64_relu(S0, Wt, bk, S1, tx, ty);                // k
    __syncthreads();

    __nv_bfloat16* kb2 = g_kb + (size_t)(b * NPOS + n0) * 64;
#pragma unroll
    for (int idx = tid; idx < 4096; idx += 256) {
        int nl = idx >> 6, o = idx & 63;
        kb2[nl * 64 + o] = __float2bfloat16(S1[o * SP + nl]);
    }
}

// ===========================================================================
// mma.sync attention, 8 warps/CTA with intra-CTA split-K:
//  warp w: rows (w&3)*16..+15, key half h=(w>>2) (32 keys of each 64-key tile).
//  Partial O / lsum combined additively in smem (no-rescale softmax).
// ===========================================================================
#define TSTRIDE 144          // bytes per smem tile row (72 bf16)
#define SM_Q   0             // 64*144 = 9216
#define SM_K0  9216
#define SM_K1  18432
#define SM_V0  27648
#define SM_V1  36864
#define SM_O   9216          // fp32 64x68 epilogue aliases K0/K1 (safe: after final sync)
#define SM_L   26624         // 64-float lsum array
#define ATTN_SMEM 46080

__global__ __launch_bounds__(256, 1)
void attn_mma_kernel(const float* __restrict__ gamma, float* __restrict__ out)
{
    extern __shared__ char smc[];
    const uint32_t sb = smem_u32(smc);
    const int tid = threadIdx.x;
    const int lane = tid & 31, w = tid >> 5;
    const int w4 = w & 3, h = w >> 2;
    const int b = blockIdx.x / 36;
    const int m0 = (blockIdx.x % 36) * 64;

    const char* qg = (const char*)(g_qb + (size_t)(b * NPOS + m0) * 64);
    const char* kg = (const char*)(g_kb + (size_t)b * NPOS * 64);
    const char* vg = (const char*)(g_vb + (size_t)b * 64 * NPOS);

    const float gm = THITA * gamma[0];

    // prologue: cp.async Q + K0 + V0 (each tile = 512 x 16B chunks)
#pragma unroll
    for (int it = 0; it < 2; ++it) {
        int idx = tid + it * 256;
        int row = idx >> 3, c16 = (idx & 7) * 16;
        CP16(sb + SM_Q  + row * TSTRIDE + c16, qg + row * 128 + c16);
        CP16(sb + SM_K0 + row * TSTRIDE + c16, kg + row * 128 + c16);
        CP16(sb + SM_V0 + row * TSTRIDE + c16, vg + (size_t)row * (NPOS * 2) + c16);
    }
    CP_COMMIT();
    CP_WAIT0();
    __syncthreads();

    // Q a-fragments (persistent): warp rows w4*16..+15
    uint32_t qf[4][4];
    {
        uint32_t base = sb + SM_Q + (w4 * 16 + (lane & 15)) * TSTRIDE + ((lane >> 4) << 3) * 2;
#pragma unroll
        for (int ks = 0; ks < 4; ++ks) ldsm4(qf[ks], base + ks * 32);
    }

    float O[8][4];
#pragma unroll
    for (int j = 0; j < 8; ++j)
#pragma unroll
        for (int e = 0; e < 4; ++e) O[j][e] = 0.f;
    float lsum0 = 0.f, lsum1 = 0.f;

    const uint32_t koff[2] = { SM_K0, SM_K1 };
    const uint32_t voff[2] = { SM_V0, SM_V1 };
    const int bro = ((lane & 16) >> 1) + (lane & 7);
    const int bco = (lane & 8) * 2;

    for (int i = 0; i < 36; ++i) {
        const int buf = i & 1;
        if (i < 35) {
            const int n1 = (i + 1) * 64;
            const char* kgs = kg + (size_t)n1 * 128;
#pragma unroll
            for (int it = 0; it < 2; ++it) {
                int idx = tid + it * 256;
                int row = idx >> 3, c16 = (idx & 7) * 16;
                CP16(sb + koff[buf ^ 1] + row * TSTRIDE + c16, kgs + row * 128 + c16);
                CP16(sb + voff[buf ^ 1] + row * TSTRIDE + c16,
                     vg + (size_t)row * (NPOS * 2) + n1 * 2 + c16);
            }
            CP_COMMIT();
        }

        // S = Q K^T for this warp's 32-key half (4 n-tiles of 8 keys)
        float S[4][4];
#pragma unroll
        for (int j = 0; j < 4; ++j)
#pragma unroll
            for (int e = 0; e < 4; ++e) S[j][e] = 0.f;
#pragma unroll
        for (int ks = 0; ks < 4; ++ks) {
#pragma unroll
            for (int p = 0; p < 2; ++p) {
                uint32_t kb[4];
                ldsm4(kb, sb + koff[buf] + (h * 32 + 16 * p + bro) * TSTRIDE + ks * 32 + bco);
                mma16816(S[2 * p],     qf[ks], kb[0], kb[1]);
                mma16816(S[2 * p + 1], qf[ks], kb[2], kb[3]);
            }
        }

        // P = exp(S - 16): row sums + repack c-frag -> a-frag (bf16)
        uint32_t P[2][4];
#pragma unroll
        for (int j = 0; j < 4; ++j) {
            float e0 = __expf(S[j][0] - EXP_SHIFT);
            float e1 = __expf(S[j][1] - EXP_SHIFT);
            float e2 = __expf(S[j][2] - EXP_SHIFT);
            float e3 = __expf(S[j][3] - EXP_SHIFT);
            lsum0 += e0 + e1;
            lsum1 += e2 + e3;
            P[j >> 1][(j & 1) * 2 + 0] = pack_bf16x2(e0, e1);
            P[j >> 1][(j & 1) * 2 + 1] = pack_bf16x2(e2, e3);
        }

        // O += P V  (V columns = this warp's 32 keys; 8 chan-tiles of 8)
#pragma unroll
        for (int step = 0; step < 2; ++step) {
#pragma unroll
            for (int p = 0; p < 4; ++p) {
                uint32_t vb[4];
                ldsm4(vb, sb + voff[buf] + (16 * p + bro) * TSTRIDE + h * 64 + step * 32 + bco);
                mma16816(O[2 * p],     P[step], vb[0], vb[1]);
                mma16816(O[2 * p + 1], P[step], vb[2], vb[3]);
            }
        }

        if (i < 35) CP_WAIT0();
        __syncthreads();
    }

    // reduce lsum over the 4 lanes sharing each row
    lsum0 += __shfl_xor_sync(0xffffffffu, lsum0, 1);
    lsum0 += __shfl_xor_sync(0xffffffffu, lsum0, 2);
    lsum1 += __shfl_xor_sync(0xffffffffu, lsum1, 1);
    lsum1 += __shfl_xor_sync(0xffffffffu, lsum1, 2);

    // epilogue: additive combine of the two key-half partials in smem
    float* so  = (float*)(smc + SM_O);
    float* lar = (float*)(smc + SM_L);
    const int g = lane >> 2, t2 = (lane & 3) * 2;
    const int m_lo = w4 * 16 + g, m_hi = m_lo + 8;

    if (h == 0) {
#pragma unroll
        for (int j = 0; j < 8; ++j) {
            int c = 8 * j + t2;
            so[c * 68 + m_lo]       = O[j][0];
            so[(c + 1) * 68 + m_lo] = O[j][1];
            so[c * 68 + m_hi]       = O[j][2];
            so[(c + 1) * 68 + m_hi] = O[j][3];
        }
        if ((lane & 3) == 0) { lar[m_lo] = lsum0; lar[m_hi] = lsum1; }
    }
    __syncthreads();
    if (h == 1) {
#pragma unroll
        for (int j = 0; j < 8; ++j) {
            int c = 8 * j + t2;
            so[c * 68 + m_lo]       += O[j][0];
            so[(c + 1) * 68 + m_lo] += O[j][1];
            so[c * 68 + m_hi]       += O[j][2];
            so[(c + 1) * 68 + m_hi] += O[j][3];
        }
        if ((lane & 3) == 0) { lar[m_lo] += lsum0; lar[m_hi] += lsum1; }
    }
    __syncthreads();
    if (tid < 64) lar[tid] = gm / lar[tid];
    __syncthreads();

    // out[c][m] = so[c][m]*lar[m] + x1[c][m]  (coalesced float4)
    const float* x1b = g_x1 + (size_t)b * 64 * NPOS + m0;
    float* ob = out + (size_t)b * 64 * NPOS + m0;
#pragma unroll
    for (int it = 0; it < 4; ++it) {
        int idx = tid + it * 256;            // 0..1023
        int c = idx >> 4, m4 = (idx & 15) * 4;
        float4 o4 = *(const float4*)(so + c * 68 + m4);
        float4 l4 = *(const float4*)(lar + m4);
        float4 xv = *(const float4*)(x1b + (size_t)c * NPOS + m4);
        float4 r;
        r.x = o4.x * l4.x + xv.x; r.y = o4.y * l4.y + xv.y;
        r.z = o4.z * l4.z + xv.z; r.w = o4.w * l4.w + xv.w;
        *(float4*)(ob + (size_t)c * NPOS + m4) = r;
    }
}

// ===========================================================================
extern "C" void kernel_launch(void* const* d_in, const int* in_sizes, int n_in,
                              void* d_out, int out_size)
{
    const float* x     = (const float*)d_in[0];
    const float* event = (const float*)d_in[1];
    const float* Wx0 = (const float*)d_in[2];
    const float* bx0 = (const float*)d_in[3];
    const float* Wx1 = (const float*)d_in[4];
    const float* bx1 = (const float*)d_in[5];
    const float* We0 = (const float*)d_in[6];
    const float* be0 = (const float*)d_in[7];
    const float* We1 = (const float*)d_in[8];
    const float* be1 = (const float*)d_in[9];
    const float* Wq  = (const float*)d_in[10];
    const float* bq  = (const float*)d_in[11];
    const float* Wk  = (const float*)d_in[12];
    const float* bk  = (const float*)d_in[13];
    const float* Wv  = (const float*)d_in[14];
    const float* bv  = (const float*)d_in[15];
    const float* gamma = (const float*)d_in[16];
    float* out = (float*)d_out;

    const int proj_smem = (2 * 64 * SP + 64 * WP) * (int)sizeof(float);

    cudaFuncSetAttribute(proj_kernel, cudaFuncAttributeMaxDynamicSharedMemorySize, proj_smem);
    cudaFuncSetAttribute(attn_mma_kernel, cudaFuncAttributeMaxDynamicSharedMemorySize, ATTN_SMEM);

    proj_kernel<<<144, 256, proj_smem>>>(x, event,
                                         Wx0, bx0, Wx1, bx1,
                                         We0, be0, We1, be1,
                                         Wq, bq, Wk, bk, Wv, bv);
    attn_mma_kernel<<<144, 256, ATTN_SMEM>>>(gamma, out);
}

// round 6
// speedup vs baseline: 4.0162x; 1.0955x over previous
#include <cuda_runtime.h>
#include <cuda_bf16.h>
#include <cstdint>

#define THITA 0.0001f
#define NPOS 2304
#define SP 68
#define WP 65
#define EXP_SHIFT 16.0f

// Scratch (device globals)
__device__ __align__(128) __nv_bfloat16 g_qb[4 * 2304 * 64];  // (B, N, C)
__device__ __align__(128) __nv_bfloat16 g_kb[4 * 2304 * 64];  // (B, N, C)
__device__ __align__(128) __nv_bfloat16 g_vb[4 * 64 * 2304];  // (B, C, N)
__device__ __align__(128) float         g_x1[4 * 64 * 2304];  // (B, C, N)

// ===========================================================================
// Generic-PTX helpers (compute_103-safe: no tcgen05)
// ===========================================================================
__device__ __forceinline__ uint32_t smem_u32(const void* p) {
    uint32_t a;
    asm("{ .reg .u64 t; cvta.to.shared.u64 t, %1; cvt.u32.u64 %0, t; }" : "=r"(a) : "l"(p));
    return a;
}

#define CP16(dst, src) asm volatile("cp.async.cg.shared.global [%0], [%1], 16;" :: "r"(dst), "l"(src))
#define CP_COMMIT()    asm volatile("cp.async.commit_group;" ::: "memory")
#define CP_WAIT0()     asm volatile("cp.async.wait_group 0;" ::: "memory")
#define CP_WAIT1()     asm volatile("cp.async.wait_group 1;" ::: "memory")

__device__ __forceinline__ void ldsm4(uint32_t* r, uint32_t addr) {
    asm volatile("ldmatrix.sync.aligned.m8n8.x4.shared.b16 {%0,%1,%2,%3}, [%4];"
                 : "=r"(r[0]), "=r"(r[1]), "=r"(r[2]), "=r"(r[3]) : "r"(addr));
}

__device__ __forceinline__ void mma16816(float* c, const uint32_t* a,
                                         uint32_t b0, uint32_t b1) {
    asm volatile("mma.sync.aligned.m16n8k16.row.col.f32.bf16.bf16.f32 "
                 "{%0,%1,%2,%3}, {%4,%5,%6,%7}, {%8,%9}, {%0,%1,%2,%3};"
                 : "+f"(c[0]), "+f"(c[1]), "+f"(c[2]), "+f"(c[3])
                 : "r"(a[0]), "r"(a[1]), "r"(a[2]), "r"(a[3]), "r"(b0), "r"(b1));
}

__device__ __forceinline__ uint32_t pack_bf16x2(float lo, float hi) {
    uint32_t r;
    asm("cvt.rn.bf16x2.f32 %0, %1, %2;" : "=r"(r) : "f"(hi), "f"(lo));
    return r;
}

// ===========================================================================
// Projection kernel (unchanged)
// ===========================================================================
__device__ __forceinline__ void gemm64_relu(
    const float* __restrict__ In, const float* __restrict__ Wt,
    const float* __restrict__ bias, float* __restrict__ Out, int tx, int ty)
{
    float acc[4][4];
#pragma unroll
    for (int i = 0; i < 4; i++)
#pragma unroll
        for (int j = 0; j < 4; j++) acc[i][j] = 0.f;
#pragma unroll 16
    for (int c = 0; c < 64; ++c) {
        float4 xv = *reinterpret_cast<const float4*>(In + c * SP + tx * 4);
        float w0 = Wt[c * WP + ty * 4 + 0];
        float w1 = Wt[c * WP + ty * 4 + 1];
        float w2 = Wt[c * WP + ty * 4 + 2];
        float w3 = Wt[c * WP + ty * 4 + 3];
        acc[0][0] += w0 * xv.x; acc[0][1] += w0 * xv.y; acc[0][2] += w0 * xv.z; acc[0][3] += w0 * xv.w;
        acc[1][0] += w1 * xv.x; acc[1][1] += w1 * xv.y; acc[1][2] += w1 * xv.z; acc[1][3] += w1 * xv.w;
        acc[2][0] += w2 * xv.x; acc[2][1] += w2 * xv.y; acc[2][2] += w2 * xv.z; acc[2][3] += w2 * xv.w;
        acc[3][0] += w3 * xv.x; acc[3][1] += w3 * xv.y; acc[3][2] += w3 * xv.z; acc[3][3] += w3 * xv.w;
    }
#pragma unroll
    for (int i = 0; i < 4; i++) {
        float bb = bias[ty * 4 + i];
        float4 o4;
        o4.x = fmaxf(acc[i][0] + bb, 0.f);
        o4.y = fmaxf(acc[i][1] + bb, 0.f);
        o4.z = fmaxf(acc[i][2] + bb, 0.f);
        o4.w = fmaxf(acc[i][3] + bb, 0.f);
        *reinterpret_cast<float4*>(Out + (ty * 4 + i) * SP + tx * 4) = o4;
    }
}

__device__ __forceinline__ void loadWt(const float* __restrict__ Wg,
                                       float* __restrict__ Wt, int tid)
{
#pragma unroll
    for (int idx = tid; idx < 4096; idx += 256) {
        int o = idx >> 6, c = idx & 63;
        Wt[c * WP + o] = Wg[idx];
    }
}

__global__ __launch_bounds__(256, 1)
void proj_kernel(const float* __restrict__ x, const float* __restrict__ event,
                 const float* __restrict__ Wx0, const float* __restrict__ bx0,
                 const float* __restrict__ Wx1, const float* __restrict__ bx1,
                 const float* __restrict__ We0, const float* __restrict__ be0,
                 const float* __restrict__ We1, const float* __restrict__ be1,
                 const float* __restrict__ Wq,  const float* __restrict__ bq,
                 const float* __restrict__ Wk,  const float* __restrict__ bk,
                 const float* __restrict__ Wv,  const float* __restrict__ bv)
{
    extern __shared__ float sm[];
    float* S0 = sm;
    float* S1 = S0 + 64 * SP;
    float* Wt = S1 + 64 * SP;

    int tid = threadIdx.x;
    int tx = tid & 15, ty = tid >> 4;
    int b = blockIdx.x / 36;
    int n0 = (blockIdx.x % 36) * 64;

    const float* xb = x + b * 64 * NPOS + n0;
#pragma unroll
    for (int idx = tid; idx < 4096; idx += 256) {
        int c = idx >> 6, j = idx & 63;
        S0[c * SP + j] = xb[c * NPOS + j];
    }
    loadWt(Wx0, Wt, tid);
    __syncthreads();
    gemm64_relu(S0, Wt, bx0, S1, tx, ty);               // x1
    __syncthreads();

    float* x1b = g_x1 + b * 64 * NPOS + n0;
#pragma unroll
    for (int idx = tid; idx < 4096; idx += 256) {
        int c = idx >> 6, j = idx & 63;
        x1b[c * NPOS + j] = S1[c * SP + j];
    }
    loadWt(Wx1, Wt, tid);
    __syncthreads();
    gemm64_relu(S1, Wt, bx1, S0, tx, ty);               // x2
    __syncthreads();

    loadWt(Wq, Wt, tid);
    __syncthreads();
    gemm64_relu(S0, Wt, bq, S1, tx, ty);                // q
    __syncthreads();

    __nv_bfloat16* qb = g_qb + (size_t)(b * NPOS + n0) * 64;
#pragma unroll
    for (int idx = tid; idx < 4096; idx += 256) {
        int nl = idx >> 6, o = idx & 63;
        qb[nl * 64 + o] = __float2bfloat16(S1[o * SP + nl]);
    }
    loadWt(Wv, Wt, tid);
    __syncthreads();
    gemm64_relu(S0, Wt, bv, S1, tx, ty);                // v
    __syncthreads();

    __nv_bfloat16* vb = g_vb + (size_t)b * 64 * NPOS + n0;
#pragma unroll
    for (int idx = tid; idx < 4096; idx += 256) {
        int c = idx >> 6, j = idx & 63;
        vb[(size_t)c * NPOS + j] = __float2bfloat16(S1[c * SP + j]);
    }

    const float* eb = event + (long)b * 64 * 768 * 768;
#pragma unroll
    for (int idx = tid; idx < 4096; idx += 256) {
        int c = idx >> 6, j = idx & 63;
        int n = n0 + j;
        int hh = n / 48;
        int ww = n - hh * 48;
        S0[c * SP + j] = eb[((long)c * 768 + hh * 16) * 768 + ww * 16];
    }
    loadWt(We0, Wt, tid);
    __syncthreads();
    gemm64_relu(S0, Wt, be0, S1, tx, ty);               // ef0
    __syncthreads();
    loadWt(We1, Wt, tid);
    __syncthreads();
    gemm64_relu(S1, Wt, be1, S0, tx, ty);               // ef1
    __syncthreads();
    loadWt(Wk, Wt, tid);
    __syncthreads();
    gemm64_relu(S0, Wt, bk, S1, tx, ty);                // k
    __syncthreads();

    __nv_bfloat16* kb2 = g_kb + (size_t)(b * NPOS + n0) * 64;
#pragma unroll
    for (int idx = tid; idx < 4096; idx += 256) {
        int nl = idx >> 6, o = idx & 63;
        kb2[nl * 64 + o] = __float2bfloat16(S1[o * SP + nl]);
    }
}

// ===========================================================================
// mma.sync attention, 8 warps/CTA, intra-CTA split-K, 3-stage cp.async
// pipeline (loads run 2 key-blocks ahead; wait_group 1 off critical path).
// ===========================================================================
#define TSTRIDE 144          // bytes per smem tile row (72 bf16)
#define SM_Q   0             // 64*144 = 9216
#define SM_K   9216          // 3 K stages: 9216 each -> ends 36864
#define SM_V   36864         // 3 V stages: 9216 each -> ends 64512
#define SM_O   9216          // fp32 64x68 epilogue aliases K stages (after final sync)
#define SM_L   26624         // 64-float lsum (+64 floats spare)  within K region
#define ATTN_SMEM 64512

__global__ __launch_bounds__(256, 1)
void attn_mma_kernel(const float* __restrict__ gamma, float* __restrict__ out)
{
    extern __shared__ char smc[];
    const uint32_t sb = smem_u32(smc);
    const int tid = threadIdx.x;
    const int lane = tid & 31, w = tid >> 5;
    const int w4 = w & 3, h = w >> 2;
    const int b = blockIdx.x / 36;
    const int m0 = (blockIdx.x % 36) * 64;

    const char* qg = (const char*)(g_qb + (size_t)(b * NPOS + m0) * 64);
    const char* kg = (const char*)(g_kb + (size_t)b * NPOS * 64);
    const char* vg = (const char*)(g_vb + (size_t)b * 64 * NPOS);

    const float gm = THITA * gamma[0];

    // per-thread copy coordinates (2 x 16B chunks per tile)
    const int row0 = tid >> 3,            c16_0 = (tid & 7) * 16;
    const int row1 = (tid + 256) >> 3,    c16_1 = (tid & 7) * 16;

    // ---- prologue: group0 = Q + K0 + V0, group1 = K1 + V1 ----
    CP16(sb + SM_Q + row0 * TSTRIDE + c16_0, qg + row0 * 128 + c16_0);
    CP16(sb + SM_Q + row1 * TSTRIDE + c16_1, qg + row1 * 128 + c16_1);
    CP16(sb + SM_K + row0 * TSTRIDE + c16_0, kg + row0 * 128 + c16_0);
    CP16(sb + SM_K + row1 * TSTRIDE + c16_1, kg + row1 * 128 + c16_1);
    CP16(sb + SM_V + row0 * TSTRIDE + c16_0, vg + (size_t)row0 * (NPOS * 2) + c16_0);
    CP16(sb + SM_V + row1 * TSTRIDE + c16_1, vg + (size_t)row1 * (NPOS * 2) + c16_1);
    CP_COMMIT();
    {
        const char* kgs = kg + (size_t)64 * 128;
        CP16(sb + SM_K + 9216 + row0 * TSTRIDE + c16_0, kgs + row0 * 128 + c16_0);
        CP16(sb + SM_K + 9216 + row1 * TSTRIDE + c16_1, kgs + row1 * 128 + c16_1);
        CP16(sb + SM_V + 9216 + row0 * TSTRIDE + c16_0, vg + (size_t)row0 * (NPOS * 2) + 128 + c16_0);
        CP16(sb + SM_V + 9216 + row1 * TSTRIDE + c16_1, vg + (size_t)row1 * (NPOS * 2) + 128 + c16_1);
    }
    CP_COMMIT();
    CP_WAIT1();           // group0 (Q,K0,V0) complete; group1 in flight
    __syncthreads();

    // Q a-fragments (persistent): warp rows w4*16..+15
    uint32_t qf[4][4];
    {
        uint32_t base = sb + SM_Q + (w4 * 16 + (lane & 15)) * TSTRIDE + ((lane >> 4) << 3) * 2;
#pragma unroll
        for (int ks = 0; ks < 4; ++ks) ldsm4(qf[ks], base + ks * 32);
    }

    float O[8][4];
#pragma unroll
    for (int j = 0; j < 8; ++j)
#pragma unroll
        for (int e = 0; e < 4; ++e) O[j][e] = 0.f;
    float lsum0 = 0.f, lsum1 = 0.f;

    const int bro = ((lane & 16) >> 1) + (lane & 7);
    const int bco = (lane & 8) * 2;

    int cur = 0;          // stage being consumed
    int nxt2 = 2;         // stage being filled (block i+2)

    for (int i = 0; i < 36; ++i) {
        // issue loads for block i+2 (empty group in tail keeps counts uniform)
        if (i + 2 < 36) {
            const int n2 = (i + 2) * 64;
            const char* kgs = kg + (size_t)n2 * 128;
            const uint32_t ko = sb + SM_K + nxt2 * 9216;
            const uint32_t vo = sb + SM_V + nxt2 * 9216;
            CP16(ko + row0 * TSTRIDE + c16_0, kgs + row0 * 128 + c16_0);
            CP16(ko + row1 * TSTRIDE + c16_1, kgs + row1 * 128 + c16_1);
            CP16(vo + row0 * TSTRIDE + c16_0, vg + (size_t)row0 * (NPOS * 2) + n2 * 2 + c16_0);
            CP16(vo + row1 * TSTRIDE + c16_1, vg + (size_t)row1 * (NPOS * 2) + n2 * 2 + c16_1);
        }
        CP_COMMIT();

        const uint32_t kbase = sb + SM_K + cur * 9216;
        const uint32_t vbase = sb + SM_V + cur * 9216;

        // S = Q K^T for this warp's 32-key half (4 n-tiles of 8 keys)
        float S[4][4];
#pragma unroll
        for (int j = 0; j < 4; ++j)
#pragma unroll
            for (int e = 0; e < 4; ++e) S[j][e] = 0.f;
#pragma unroll
        for (int ks = 0; ks < 4; ++ks) {
#pragma unroll
            for (int p = 0; p < 2; ++p) {
                uint32_t kb[4];
                ldsm4(kb, kbase + (h * 32 + 16 * p + bro) * TSTRIDE + ks * 32 + bco);
                mma16816(S[2 * p],     qf[ks], kb[0], kb[1]);
                mma16816(S[2 * p + 1], qf[ks], kb[2], kb[3]);
            }
        }

        // P = exp(S - 16): row sums + repack c-frag -> a-frag (bf16)
        uint32_t P[2][4];
#pragma unroll
        for (int j = 0; j < 4; ++j) {
            float e0 = __expf(S[j][0] - EXP_SHIFT);
            float e1 = __expf(S[j][1] - EXP_SHIFT);
            float e2 = __expf(S[j][2] - EXP_SHIFT);
            float e3 = __expf(S[j][3] - EXP_SHIFT);
            lsum0 += e0 + e1;
            lsum1 += e2 + e3;
            P[j >> 1][(j & 1) * 2 + 0] = pack_bf16x2(e0, e1);
            P[j >> 1][(j & 1) * 2 + 1] = pack_bf16x2(e2, e3);
        }

        // O += P V
#pragma unroll
        for (int step = 0; step < 2; ++step) {
#pragma unroll
            for (int p = 0; p < 4; ++p) {
                uint32_t vb[4];
                ldsm4(vb, vbase + (16 * p + bro) * TSTRIDE + h * 64 + step * 32 + bco);
                mma16816(O[2 * p],     P[step], vb[0], vb[1]);
                mma16816(O[2 * p + 1], P[step], vb[2], vb[3]);
            }
        }

        // wait for block i+1 only (issued 1-2 iterations ago); i+2 stays in flight
        CP_WAIT1();
        __syncthreads();

        cur = (cur == 2) ? 0 : cur + 1;
        nxt2 = (nxt2 == 2) ? 0 : nxt2 + 1;
    }

    // reduce lsum over the 4 lanes sharing each row
    lsum0 += __shfl_xor_sync(0xffffffffu, lsum0, 1);
    lsum0 += __shfl_xor_sync(0xffffffffu, lsum0, 2);
    lsum1 += __shfl_xor_sync(0xffffffffu, lsum1, 1);
    lsum1 += __shfl_xor_sync(0xffffffffu, lsum1, 2);

    // epilogue: additive combine of the two key-half partials in smem
    float* so  = (float*)(smc + SM_O);
    float* lar = (float*)(smc + SM_L);
    const int g = lane >> 2, t2 = (lane & 3) * 2;
    const int m_lo = w4 * 16 + g, m_hi = m_lo + 8;

    if (h == 0) {
#pragma unroll
        for (int j = 0; j < 8; ++j) {
            int c = 8 * j + t2;
            so[c * 68 + m_lo]       = O[j][0];
            so[(c + 1) * 68 + m_lo] = O[j][1];
            so[c * 68 + m_hi]       = O[j][2];
            so[(c + 1) * 68 + m_hi] = O[j][3];
        }
        if ((lane & 3) == 0) { lar[m_lo] = lsum0; lar[m_hi] = lsum1; }
    }
    __syncthreads();
    if (h == 1) {
#pragma unroll
        for (int j = 0; j < 8; ++j) {
            int c = 8 * j + t2;
            so[c * 68 + m_lo]       += O[j][0];
            so[(c + 1) * 68 + m_lo] += O[j][1];
            so[c * 68 + m_hi]       += O[j][2];
            so[(c + 1) * 68 + m_hi] += O[j][3];
        }
        if ((lane & 3) == 0) { lar[m_lo] += lsum0; lar[m_hi] += lsum1; }
    }
    __syncthreads();
    if (tid < 64) lar[tid] = gm / lar[tid];
    __syncthreads();

    // out[c][m] = so[c][m]*lar[m] + x1[c][m]  (coalesced float4)
    const float* x1b = g_x1 + (size_t)b * 64 * NPOS + m0;
    float* ob = out + (size_t)b * 64 * NPOS + m0;
#pragma unroll
    for (int it = 0; it < 4; ++it) {
        int idx = tid + it * 256;            // 0..1023
        int c = idx >> 4, m4 = (idx & 15) * 4;
        float4 o4 = *(const float4*)(so + c * 68 + m4);
        float4 l4 = *(const float4*)(lar + m4);
        float4 xv = *(const float4*)(x1b + (size_t)c * NPOS + m4);
        float4 r;
        r.x = o4.x * l4.x + xv.x; r.y = o4.y * l4.y + xv.y;
        r.z = o4.z * l4.z + xv.z; r.w = o4.w * l4.w + xv.w;
        *(float4*)(ob + (size_t)c * NPOS + m4) = r;
    }
}

// ===========================================================================
extern "C" void kernel_launch(void* const* d_in, const int* in_sizes, int n_in,
                              void* d_out, int out_size)
{
    const float* x     = (const float*)d_in[0];
    const float* event = (const float*)d_in[1];
    const float* Wx0 = (const float*)d_in[2];
    const float* bx0 = (const float*)d_in[3];
    const float* Wx1 = (const float*)d_in[4];
    const float* bx1 = (const float*)d_in[5];
    const float* We0 = (const float*)d_in[6];
    const float* be0 = (const float*)d_in[7];
    const float* We1 = (const float*)d_in[8];
    const float* be1 = (const float*)d_in[9];
    const float* Wq  = (const float*)d_in[10];
    const float* bq  = (const float*)d_in[11];
    const float* Wk  = (const float*)d_in[12];
    const float* bk  = (const float*)d_in[13];
    const float* Wv  = (const float*)d_in[14];
    const float* bv  = (const float*)d_in[15];
    const float* gamma = (const float*)d_in[16];
    float* out = (float*)d_out;

    const int proj_smem = (2 * 64 * SP + 64 * WP) * (int)sizeof(float);

    cudaFuncSetAttribute(proj_kernel, cudaFuncAttributeMaxDynamicSharedMemorySize, proj_smem);
    cudaFuncSetAttribute(attn_mma_kernel, cudaFuncAttributeMaxDynamicSharedMemorySize, ATTN_SMEM);

    proj_kernel<<<144, 256, proj_smem>>>(x, event,
                                         Wx0, bx0, Wx1, bx1,
                                         We0, be0, We1, be1,
                                         Wq, bq, Wk, bk, Wv, bv);
    attn_mma_kernel<<<144, 256, ATTN_SMEM>>>(gamma, out);
}

// round 7
// speedup vs baseline: 4.0190x; 1.0007x over previous
#include <cuda_runtime.h>
#include <cuda_bf16.h>
#include <cstdint>

#define THITA 0.0001f
#define NPOS 2304
#define SP 68
#define WP 65
#define EXP_SHIFT 16.0f

// Scratch (device globals)
__device__ __align__(128) __nv_bfloat16 g_qb[4 * 2304 * 64];  // (B, N, C)
__device__ __align__(128) __nv_bfloat16 g_kb[4 * 2304 * 64];  // (B, N, C)
__device__ __align__(128) __nv_bfloat16 g_vb[4 * 64 * 2304];  // (B, C, N)
__device__ __align__(128) float         g_x1[4 * 64 * 2304];  // (B, C, N)
__device__ __align__(128) float         g_part[288 * 4096];   // split-K partial O
__device__ __align__(128) float         g_lpart[288 * 64];    // split-K partial lsum

// ===========================================================================
// Generic-PTX helpers (compute_103-safe: no tcgen05)
// ===========================================================================
__device__ __forceinline__ uint32_t smem_u32(const void* p) {
    uint32_t a;
    asm("{ .reg .u64 t; cvta.to.shared.u64 t, %1; cvt.u32.u64 %0, t; }" : "=r"(a) : "l"(p));
    return a;
}

#define CP16(dst, src) asm volatile("cp.async.cg.shared.global [%0], [%1], 16;" :: "r"(dst), "l"(src))
#define CP_COMMIT()    asm volatile("cp.async.commit_group;" ::: "memory")
#define CP_WAIT1()     asm volatile("cp.async.wait_group 1;" ::: "memory")

__device__ __forceinline__ void ldsm4(uint32_t* r, uint32_t addr) {
    asm volatile("ldmatrix.sync.aligned.m8n8.x4.shared.b16 {%0,%1,%2,%3}, [%4];"
                 : "=r"(r[0]), "=r"(r[1]), "=r"(r[2]), "=r"(r[3]) : "r"(addr));
}

__device__ __forceinline__ void mma16816(float* c, const uint32_t* a,
                                         uint32_t b0, uint32_t b1) {
    asm volatile("mma.sync.aligned.m16n8k16.row.col.f32.bf16.bf16.f32 "
                 "{%0,%1,%2,%3}, {%4,%5,%6,%7}, {%8,%9}, {%0,%1,%2,%3};"
                 : "+f"(c[0]), "+f"(c[1]), "+f"(c[2]), "+f"(c[3])
                 : "r"(a[0]), "r"(a[1]), "r"(a[2]), "r"(a[3]), "r"(b0), "r"(b1));
}

__device__ __forceinline__ uint32_t pack_bf16x2(float lo, float hi) {
    uint32_t r;
    asm("cvt.rn.bf16x2.f32 %0, %1, %2;" : "=r"(r) : "f"(hi), "f"(lo));
    return r;
}

// ===========================================================================
// Projection kernel (unchanged)
// ===========================================================================
__device__ __forceinline__ void gemm64_relu(
    const float* __restrict__ In, const float* __restrict__ Wt,
    const float* __restrict__ bias, float* __restrict__ Out, int tx, int ty)
{
    float acc[4][4];
#pragma unroll
    for (int i = 0; i < 4; i++)
#pragma unroll
        for (int j = 0; j < 4; j++) acc[i][j] = 0.f;
#pragma unroll 16
    for (int c = 0; c < 64; ++c) {
        float4 xv = *reinterpret_cast<const float4*>(In + c * SP + tx * 4);
        float w0 = Wt[c * WP + ty * 4 + 0];
        float w1 = Wt[c * WP + ty * 4 + 1];
        float w2 = Wt[c * WP + ty * 4 + 2];
        float w3 = Wt[c * WP + ty * 4 + 3];
        acc[0][0] += w0 * xv.x; acc[0][1] += w0 * xv.y; acc[0][2] += w0 * xv.z; acc[0][3] += w0 * xv.w;
        acc[1][0] += w1 * xv.x; acc[1][1] += w1 * xv.y; acc[1][2] += w1 * xv.z; acc[1][3] += w1 * xv.w;
        acc[2][0] += w2 * xv.x; acc[2][1] += w2 * xv.y; acc[2][2] += w2 * xv.z; acc[2][3] += w2 * xv.w;
        acc[3][0] += w3 * xv.x; acc[3][1] += w3 * xv.y; acc[3][2] += w3 * xv.z; acc[3][3] += w3 * xv.w;
    }
#pragma unroll
    for (int i = 0; i < 4; i++) {
        float bb = bias[ty * 4 + i];
        float4 o4;
        o4.x = fmaxf(acc[i][0] + bb, 0.f);
        o4.y = fmaxf(acc[i][1] + bb, 0.f);
        o4.z = fmaxf(acc[i][2] + bb, 0.f);
        o4.w = fmaxf(acc[i][3] + bb, 0.f);
        *reinterpret_cast<float4*>(Out + (ty * 4 + i) * SP + tx * 4) = o4;
    }
}

__device__ __forceinline__ void loadWt(const float* __restrict__ Wg,
                                       float* __restrict__ Wt, int tid)
{
#pragma unroll
    for (int idx = tid; idx < 4096; idx += 256) {
        int o = idx >> 6, c = idx & 63;
        Wt[c * WP + o] = Wg[idx];
    }
}

__global__ __launch_bounds__(256, 1)
void proj_kernel(const float* __restrict__ x, const float* __restrict__ event,
                 const float* __restrict__ Wx0, const float* __restrict__ bx0,
                 const float* __restrict__ Wx1, const float* __restrict__ bx1,
                 const float* __restrict__ We0, const float* __restrict__ be0,
                 const float* __restrict__ We1, const float* __restrict__ be1,
                 const float* __restrict__ Wq,  const float* __restrict__ bq,
                 const float* __restrict__ Wk,  const float* __restrict__ bk,
                 const float* __restrict__ Wv,  const float* __restrict__ bv)
{
    extern __shared__ float sm[];
    float* S0 = sm;
    float* S1 = S0 + 64 * SP;
    float* Wt = S1 + 64 * SP;

    int tid = threadIdx.x;
    int tx = tid & 15, ty = tid >> 4;
    int b = blockIdx.x / 36;
    int n0 = (blockIdx.x % 36) * 64;

    const float* xb = x + b * 64 * NPOS + n0;
#pragma unroll
    for (int idx = tid; idx < 4096; idx += 256) {
        int c = idx >> 6, j = idx & 63;
        S0[c * SP + j] = xb[c * NPOS + j];
    }
    loadWt(Wx0, Wt, tid);
    __syncthreads();
    gemm64_relu(S0, Wt, bx0, S1, tx, ty);               // x1
    __syncthreads();

    float* x1b = g_x1 + b * 64 * NPOS + n0;
#pragma unroll
    for (int idx = tid; idx < 4096; idx += 256) {
        int c = idx >> 6, j = idx & 63;
        x1b[c * NPOS + j] = S1[c * SP + j];
    }
    loadWt(Wx1, Wt, tid);
    __syncthreads();
    gemm64_relu(S1, Wt, bx1, S0, tx, ty);               // x2
    __syncthreads();

    loadWt(Wq, Wt, tid);
    __syncthreads();
    gemm64_relu(S0, Wt, bq, S1, tx, ty);                // q
    __syncthreads();

    __nv_bfloat16* qb = g_qb + (size_t)(b * NPOS + n0) * 64;
#pragma unroll
    for (int idx = tid; idx < 4096; idx += 256) {
        int nl = idx >> 6, o = idx & 63;
        qb[nl * 64 + o] = __float2bfloat16(S1[o * SP + nl]);
    }
    loadWt(Wv, Wt, tid);
    __syncthreads();
    gemm64_relu(S0, Wt, bv, S1, tx, ty);                // v
    __syncthreads();

    __nv_bfloat16* vb = g_vb + (size_t)b * 64 * NPOS + n0;
#pragma unroll
    for (int idx = tid; idx < 4096; idx += 256) {
        int c = idx >> 6, j = idx & 63;
        vb[(size_t)c * NPOS + j] = __float2bfloat16(S1[c * SP + j]);
    }

    const float* eb = event + (long)b * 64 * 768 * 768;
#pragma unroll
    for (int idx = tid; idx < 4096; idx += 256) {
        int c = idx >> 6, j = idx & 63;
        int n = n0 + j;
        int hh = n / 48;
        int ww = n - hh * 48;
        S0[c * SP + j] = eb[((long)c * 768 + hh * 16) * 768 + ww * 16];
    }
    loadWt(We0, Wt, tid);
    __syncthreads();
    gemm64_relu(S0, Wt, be0, S1, tx, ty);               // ef0
    __syncthreads();
    loadWt(We1, Wt, tid);
    __syncthreads();
    gemm64_relu(S1, Wt, be1, S0, tx, ty);               // ef1
    __syncthreads();
    loadWt(Wk, Wt, tid);
    __syncthreads();
    gemm64_relu(S0, Wt, bk, S1, tx, ty);                // k
    __syncthreads();

    __nv_bfloat16* kb2 = g_kb + (size_t)(b * NPOS + n0) * 64;
#pragma unroll
    for (int idx = tid; idx < 4096; idx += 256) {
        int nl = idx >> 6, o = idx & 63;
        kb2[nl * 64 + o] = __float2bfloat16(S1[o * SP + nl]);
    }
}

// ===========================================================================
// mma.sync attention, grid=288 (2 key-halves per (b,mtile)), 8 warps/CTA,
// intra-CTA split-K, 3-stage cp.async pipeline, 2 CTAs/SM.
// Each CTA processes 1152 keys (18 iterations), writes raw partial O + lsum.
// ===========================================================================
#define TSTRIDE 144          // bytes per smem tile row (72 bf16)
#define SM_Q   0             // 64*144 = 9216
#define SM_K   9216          // 3 K stages -> ends 36864
#define SM_V   36864         // 3 V stages -> ends 64512
#define SM_O   9216          // fp32 64x68 epilogue aliases K stages
#define SM_L   26624         // 64-float lsum within K region
#define ATTN_SMEM 64512
#define KITERS 18

__global__ __launch_bounds__(256, 2)
void attn_mma_kernel()
{
    extern __shared__ char smc[];
    const uint32_t sb = smem_u32(smc);
    const int tid = threadIdx.x;
    const int lane = tid & 31, w = tid >> 5;
    const int w4 = w & 3, h = w >> 2;
    const int b   = blockIdx.x / 72;
    const int rem = blockIdx.x % 72;
    const int m0  = (rem >> 1) * 64;
    const int kh  = rem & 1;
    const int nbase = kh * 1152;

    const char* qg = (const char*)(g_qb + (size_t)(b * NPOS + m0) * 64);
    const char* kg = (const char*)(g_kb + (size_t)(b * NPOS + nbase) * 64);
    const char* vg = (const char*)(g_vb + (size_t)b * 64 * NPOS) + nbase * 2;

    // per-thread copy coordinates (2 x 16B chunks per tile)
    const int row0 = tid >> 3,         c16_0 = (tid & 7) * 16;
    const int row1 = (tid + 256) >> 3, c16_1 = (tid & 7) * 16;

    // ---- prologue: group0 = Q + K0 + V0, group1 = K1 + V1 ----
    CP16(sb + SM_Q + row0 * TSTRIDE + c16_0, qg + row0 * 128 + c16_0);
    CP16(sb + SM_Q + row1 * TSTRIDE + c16_1, qg + row1 * 128 + c16_1);
    CP16(sb + SM_K + row0 * TSTRIDE + c16_0, kg + row0 * 128 + c16_0);
    CP16(sb + SM_K + row1 * TSTRIDE + c16_1, kg + row1 * 128 + c16_1);
    CP16(sb + SM_V + row0 * TSTRIDE + c16_0, vg + (size_t)row0 * (NPOS * 2) + c16_0);
    CP16(sb + SM_V + row1 * TSTRIDE + c16_1, vg + (size_t)row1 * (NPOS * 2) + c16_1);
    CP_COMMIT();
    {
        const char* kgs = kg + (size_t)64 * 128;
        CP16(sb + SM_K + 9216 + row0 * TSTRIDE + c16_0, kgs + row0 * 128 + c16_0);
        CP16(sb + SM_K + 9216 + row1 * TSTRIDE + c16_1, kgs + row1 * 128 + c16_1);
        CP16(sb + SM_V + 9216 + row0 * TSTRIDE + c16_0, vg + (size_t)row0 * (NPOS * 2) + 128 + c16_0);
        CP16(sb + SM_V + 9216 + row1 * TSTRIDE + c16_1, vg + (size_t)row1 * (NPOS * 2) + 128 + c16_1);
    }
    CP_COMMIT();
    CP_WAIT1();
    __syncthreads();

    // Q a-fragments (persistent)
    uint32_t qf[4][4];
    {
        uint32_t base = sb + SM_Q + (w4 * 16 + (lane & 15)) * TSTRIDE + ((lane >> 4) << 3) * 2;
#pragma unroll
        for (int ks = 0; ks < 4; ++ks) ldsm4(qf[ks], base + ks * 32);
    }

    float O[8][4];
#pragma unroll
    for (int j = 0; j < 8; ++j)
#pragma unroll
        for (int e = 0; e < 4; ++e) O[j][e] = 0.f;
    float lsum0 = 0.f, lsum1 = 0.f;

    const int bro = ((lane & 16) >> 1) + (lane & 7);
    const int bco = (lane & 8) * 2;

    int cur = 0, nxt2 = 2;

    for (int i = 0; i < KITERS; ++i) {
        if (i + 2 < KITERS) {
            const int n2 = (i + 2) * 64;
            const char* kgs = kg + (size_t)n2 * 128;
            const uint32_t ko = sb + SM_K + nxt2 * 9216;
            const uint32_t vo = sb + SM_V + nxt2 * 9216;
            CP16(ko + row0 * TSTRIDE + c16_0, kgs + row0 * 128 + c16_0);
            CP16(ko + row1 * TSTRIDE + c16_1, kgs + row1 * 128 + c16_1);
            CP16(vo + row0 * TSTRIDE + c16_0, vg + (size_t)row0 * (NPOS * 2) + n2 * 2 + c16_0);
            CP16(vo + row1 * TSTRIDE + c16_1, vg + (size_t)row1 * (NPOS * 2) + n2 * 2 + c16_1);
        }
        CP_COMMIT();

        const uint32_t kbase = sb + SM_K + cur * 9216;
        const uint32_t vbase = sb + SM_V + cur * 9216;

        float S[4][4];
#pragma unroll
        for (int j = 0; j < 4; ++j)
#pragma unroll
            for (int e = 0; e < 4; ++e) S[j][e] = 0.f;
#pragma unroll
        for (int ks = 0; ks < 4; ++ks) {
#pragma unroll
            for (int p = 0; p < 2; ++p) {
                uint32_t kb[4];
                ldsm4(kb, kbase + (h * 32 + 16 * p + bro) * TSTRIDE + ks * 32 + bco);
                mma16816(S[2 * p],     qf[ks], kb[0], kb[1]);
                mma16816(S[2 * p + 1], qf[ks], kb[2], kb[3]);
            }
        }

        uint32_t P[2][4];
#pragma unroll
        for (int j = 0; j < 4; ++j) {
            float e0 = __expf(S[j][0] - EXP_SHIFT);
            float e1 = __expf(S[j][1] - EXP_SHIFT);
            float e2 = __expf(S[j][2] - EXP_SHIFT);
            float e3 = __expf(S[j][3] - EXP_SHIFT);
            lsum0 += e0 + e1;
            lsum1 += e2 + e3;
            P[j >> 1][(j & 1) * 2 + 0] = pack_bf16x2(e0, e1);
            P[j >> 1][(j & 1) * 2 + 1] = pack_bf16x2(e2, e3);
        }

#pragma unroll
        for (int step = 0; step < 2; ++step) {
#pragma unroll
            for (int p = 0; p < 4; ++p) {
                uint32_t vb[4];
                ldsm4(vb, vbase + (16 * p + bro) * TSTRIDE + h * 64 + step * 32 + bco);
                mma16816(O[2 * p],     P[step], vb[0], vb[1]);
                mma16816(O[2 * p + 1], P[step], vb[2], vb[3]);
            }
        }

        CP_WAIT1();
        __syncthreads();

        cur = (cur == 2) ? 0 : cur + 1;
        nxt2 = (nxt2 == 2) ? 0 : nxt2 + 1;
    }

    // reduce lsum over the 4 lanes sharing each row
    lsum0 += __shfl_xor_sync(0xffffffffu, lsum0, 1);
    lsum0 += __shfl_xor_sync(0xffffffffu, lsum0, 2);
    lsum1 += __shfl_xor_sync(0xffffffffu, lsum1, 1);
    lsum1 += __shfl_xor_sync(0xffffffffu, lsum1, 2);

    // combine the two intra-CTA key-half partials in smem (raw, unnormalized)
    float* so  = (float*)(smc + SM_O);
    float* lar = (float*)(smc + SM_L);
    const int g = lane >> 2, t2 = (lane & 3) * 2;
    const int m_lo = w4 * 16 + g, m_hi = m_lo + 8;

    if (h == 0) {
#pragma unroll
        for (int j = 0; j < 8; ++j) {
            int c = 8 * j + t2;
            so[c * 68 + m_lo]       = O[j][0];
            so[(c + 1) * 68 + m_lo] = O[j][1];
            so[c * 68 + m_hi]       = O[j][2];
            so[(c + 1) * 68 + m_hi] = O[j][3];
        }
        if ((lane & 3) == 0) { lar[m_lo] = lsum0; lar[m_hi] = lsum1; }
    }
    __syncthreads();
    if (h == 1) {
#pragma unroll
        for (int j = 0; j < 8; ++j) {
            int c = 8 * j + t2;
            so[c * 68 + m_lo]       += O[j][0];
            so[(c + 1) * 68 + m_lo] += O[j][1];
            so[c * 68 + m_hi]       += O[j][2];
            so[(c + 1) * 68 + m_hi] += O[j][3];
        }
        if ((lane & 3) == 0) { lar[m_lo] += lsum0; lar[m_hi] += lsum1; }
    }
    __syncthreads();

    // write raw partials to global scratch
    float* pb = g_part + (size_t)blockIdx.x * 4096;
#pragma unroll
    for (int it = 0; it < 4; ++it) {
        int idx = tid + it * 256;
        int c = idx >> 4, m4 = (idx & 15) * 4;
        *(float4*)(pb + c * 64 + m4) = *(const float4*)(so + c * 68 + m4);
    }
    if (tid < 64) g_lpart[blockIdx.x * 64 + tid] = lar[tid];
}

// ===========================================================================
// Combine kernel: out = (O0+O1) * gm/(l0+l1) + x1
// ===========================================================================
__global__ __launch_bounds__(256, 4)
void combine_kernel(const float* __restrict__ gamma, float* __restrict__ out)
{
    __shared__ float linv[64];
    const int tid = threadIdx.x;
    const int b = blockIdx.x / 36;
    const int m0 = (blockIdx.x % 36) * 64;
    const int pair = blockIdx.x * 2;

    if (tid < 64) {
        float l = g_lpart[pair * 64 + tid] + g_lpart[(pair + 1) * 64 + tid];
        linv[tid] = (THITA * gamma[0]) / l;
    }
    __syncthreads();

    const float* p0 = g_part + (size_t)pair * 4096;
    const float* p1 = p0 + 4096;
    const float* x1b = g_x1 + (size_t)b * 64 * NPOS + m0;
    float* ob = out + (size_t)b * 64 * NPOS + m0;

#pragma unroll
    for (int it = 0; it < 4; ++it) {
        int idx = tid + it * 256;
        int c = idx >> 4, m4 = (idx & 15) * 4;
        float4 a4 = *(const float4*)(p0 + c * 64 + m4);
        float4 b4 = *(const float4*)(p1 + c * 64 + m4);
        float4 l4 = *(const float4*)(linv + m4);
        float4 xv = *(const float4*)(x1b + (size_t)c * NPOS + m4);
        float4 r;
        r.x = (a4.x + b4.x) * l4.x + xv.x;
        r.y = (a4.y + b4.y) * l4.y + xv.y;
        r.z = (a4.z + b4.z) * l4.z + xv.z;
        r.w = (a4.w + b4.w) * l4.w + xv.w;
        *(float4*)(ob + (size_t)c * NPOS + m4) = r;
    }
}

// ===========================================================================
extern "C" void kernel_launch(void* const* d_in, const int* in_sizes, int n_in,
                              void* d_out, int out_size)
{
    const float* x     = (const float*)d_in[0];
    const float* event = (const float*)d_in[1];
    const float* Wx0 = (const float*)d_in[2];
    const float* bx0 = (const float*)d_in[3];
    const float* Wx1 = (const float*)d_in[4];
    const float* bx1 = (const float*)d_in[5];
    const float* We0 = (const float*)d_in[6];
    const float* be0 = (const float*)d_in[7];
    const float* We1 = (const float*)d_in[8];
    const float* be1 = (const float*)d_in[9];
    const float* Wq  = (const float*)d_in[10];
    const float* bq  = (const float*)d_in[11];
    const float* Wk  = (const float*)d_in[12];
    const float* bk  = (const float*)d_in[13];
    const float* Wv  = (const float*)d_in[14];
    const float* bv  = (const float*)d_in[15];
    const float* gamma = (const float*)d_in[16];
    float* out = (float*)d_out;

    const int proj_smem = (2 * 64 * SP + 64 * WP) * (int)sizeof(float);

    cudaFuncSetAttribute(proj_kernel, cudaFuncAttributeMaxDynamicSharedMemorySize, proj_smem);
    cudaFuncSetAttribute(attn_mma_kernel, cudaFuncAttributeMaxDynamicSharedMemorySize, ATTN_SMEM);

    proj_kernel<<<144, 256, proj_smem>>>(x, event,
                                         Wx0, bx0, Wx1, bx1,
                                         We0, be0, We1, be1,
                                         Wq, bq, Wk, bk, Wv, bv);
    attn_mma_kernel<<<288, 256, ATTN_SMEM>>>();
    combine_kernel<<<144, 256>>>(gamma, out);
}

// round 8
// speedup vs baseline: 4.8964x; 1.2183x over previous
#include <cuda_runtime.h>
#include <cuda_bf16.h>
#include <cstdint>

#define THITA 0.0001f
#define NPOS 2304
#define SP 68
#define WP 65
#define EXP_SHIFT 16.0f

// Scratch (device globals)
__device__ __align__(128) __nv_bfloat16 g_qb[4 * 2304 * 64];  // (B, N, C)
__device__ __align__(128) __nv_bfloat16 g_kb[4 * 2304 * 64];  // (B, N, C)
__device__ __align__(128) __nv_bfloat16 g_vb[4 * 64 * 2304];  // (B, C, N)
__device__ __align__(128) float         g_x1[4 * 64 * 2304];  // (B, C, N)
__device__ __align__(128) float         g_part[288 * 4096];   // split-K partial O
__device__ __align__(128) float         g_lpart[288 * 64];    // split-K partial lsum

// ===========================================================================
// Generic-PTX helpers (compute_103-safe)
// ===========================================================================
__device__ __forceinline__ uint32_t smem_u32(const void* p) {
    uint32_t a;
    asm("{ .reg .u64 t; cvta.to.shared.u64 t, %1; cvt.u32.u64 %0, t; }" : "=r"(a) : "l"(p));
    return a;
}

#define CP16(dst, src) asm volatile("cp.async.cg.shared.global [%0], [%1], 16;" :: "r"(dst), "l"(src))
#define CP_COMMIT()    asm volatile("cp.async.commit_group;" ::: "memory")
#define CP_WAIT1()     asm volatile("cp.async.wait_group 1;" ::: "memory")

__device__ __forceinline__ void ldsm4(uint32_t* r, uint32_t addr) {
    asm volatile("ldmatrix.sync.aligned.m8n8.x4.shared.b16 {%0,%1,%2,%3}, [%4];"
                 : "=r"(r[0]), "=r"(r[1]), "=r"(r[2]), "=r"(r[3]) : "r"(addr));
}

__device__ __forceinline__ void mma16816(float* c, const uint32_t* a,
                                         uint32_t b0, uint32_t b1) {
    asm volatile("mma.sync.aligned.m16n8k16.row.col.f32.bf16.bf16.f32 "
                 "{%0,%1,%2,%3}, {%4,%5,%6,%7}, {%8,%9}, {%0,%1,%2,%3};"
                 : "+f"(c[0]), "+f"(c[1]), "+f"(c[2]), "+f"(c[3])
                 : "r"(a[0]), "r"(a[1]), "r"(a[2]), "r"(a[3]), "r"(b0), "r"(b1));
}

__device__ __forceinline__ uint32_t pack_bf16x2(float lo, float hi) {
    uint32_t r;
    asm("cvt.rn.bf16x2.f32 %0, %1, %2;" : "=r"(r) : "f"(hi), "f"(lo));
    return r;
}

// ===========================================================================
// fp32 64x64 GEMM (x1 only — residual path must stay fp32-accurate)
// ===========================================================================
__device__ __forceinline__ void gemm64_relu(
    const float* __restrict__ In, const float* __restrict__ Wt,
    const float* __restrict__ bias, float* __restrict__ Out, int tx, int ty)
{
    float acc[4][4];
#pragma unroll
    for (int i = 0; i < 4; i++)
#pragma unroll
        for (int j = 0; j < 4; j++) acc[i][j] = 0.f;
#pragma unroll 16
    for (int c = 0; c < 64; ++c) {
        float4 xv = *reinterpret_cast<const float4*>(In + c * SP + tx * 4);
        float w0 = Wt[c * WP + ty * 4 + 0];
        float w1 = Wt[c * WP + ty * 4 + 1];
        float w2 = Wt[c * WP + ty * 4 + 2];
        float w3 = Wt[c * WP + ty * 4 + 3];
        acc[0][0] += w0 * xv.x; acc[0][1] += w0 * xv.y; acc[0][2] += w0 * xv.z; acc[0][3] += w0 * xv.w;
        acc[1][0] += w1 * xv.x; acc[1][1] += w1 * xv.y; acc[1][2] += w1 * xv.z; acc[1][3] += w1 * xv.w;
        acc[2][0] += w2 * xv.x; acc[2][1] += w2 * xv.y; acc[2][2] += w2 * xv.z; acc[2][3] += w2 * xv.w;
        acc[3][0] += w3 * xv.x; acc[3][1] += w3 * xv.y; acc[3][2] += w3 * xv.z; acc[3][3] += w3 * xv.w;
    }
#pragma unroll
    for (int i = 0; i < 4; i++) {
        float bb = bias[ty * 4 + i];
        float4 o4;
        o4.x = fmaxf(acc[i][0] + bb, 0.f);
        o4.y = fmaxf(acc[i][1] + bb, 0.f);
        o4.z = fmaxf(acc[i][2] + bb, 0.f);
        o4.w = fmaxf(acc[i][3] + bb, 0.f);
        *reinterpret_cast<float4*>(Out + (ty * 4 + i) * SP + tx * 4) = o4;
    }
}

__device__ __forceinline__ void loadWt(const float* __restrict__ Wg,
                                       float* __restrict__ Wt, int tid)
{
#pragma unroll
    for (int idx = tid; idx < 4096; idx += 256) {
        int o = idx >> 6, c = idx & 63;
        Wt[c * WP + o] = Wg[idx];
    }
}

// ===========================================================================
// bf16 tensor-core 64x64 GEMM + bias + relu (damped paths)
// A: smem [64 pos][72 pad] bf16 ; W: smem [64 out][72 pad] bf16 (row=n, col=k)
// Out: smem [64 pos][72 pad] bf16. Warp (w4,h): rows w4*16..+15, cols h*32..+31.
// ===========================================================================
__device__ __forceinline__ void gemm_tc(uint32_t sb, char* smc,
    uint32_t aoff, uint32_t woff, const float* __restrict__ biasS, uint32_t ooff,
    int lane, int w4, int h)
{
    const int bro = ((lane & 16) >> 1) + (lane & 7);
    const int bco = (lane & 8) * 2;
    uint32_t af[4][4];
    uint32_t abase = sb + aoff + (w4 * 16 + (lane & 15)) * 144 + ((lane >> 4) << 4);
#pragma unroll
    for (int ks = 0; ks < 4; ++ks) ldsm4(af[ks], abase + ks * 32);

    float C[4][4];
#pragma unroll
    for (int j = 0; j < 4; ++j)
#pragma unroll
        for (int e = 0; e < 4; ++e) C[j][e] = 0.f;

#pragma unroll
    for (int ks = 0; ks < 4; ++ks) {
#pragma unroll
        for (int p = 0; p < 2; ++p) {
            uint32_t wb[4];
            ldsm4(wb, sb + woff + (h * 32 + 16 * p + bro) * 144 + ks * 32 + bco);
            mma16816(C[2 * p],     af[ks], wb[0], wb[1]);
            mma16816(C[2 * p + 1], af[ks], wb[2], wb[3]);
        }
    }

    const int rl = w4 * 16 + (lane >> 2), rh = rl + 8;
#pragma unroll
    for (int j = 0; j < 4; ++j) {
        int n = h * 32 + 8 * j + (lane & 3) * 2;
        float b0 = biasS[n], b1 = biasS[n + 1];
        uint32_t u0 = pack_bf16x2(fmaxf(C[j][0] + b0, 0.f), fmaxf(C[j][1] + b1, 0.f));
        uint32_t u1 = pack_bf16x2(fmaxf(C[j][2] + b0, 0.f), fmaxf(C[j][3] + b1, 0.f));
        *(uint32_t*)(smc + ooff + rl * 144 + n * 2) = u0;
        *(uint32_t*)(smc + ooff + rh * 144 + n * 2) = u1;
    }
}

// fp32 global weight [o][c] -> smem bf16 [o][72 pad]; bias fp32 -> smem
__device__ __forceinline__ void loadW16(const float* __restrict__ Wg,
                                        const float* __restrict__ bg,
                                        char* smc, uint32_t woff, float* biasS, int tid)
{
#pragma unroll
    for (int idx = tid; idx < 4096; idx += 256) {
        int o = idx >> 6, c = idx & 63;
        *(__nv_bfloat16*)(smc + woff + o * 144 + c * 2) = __float2bfloat16(Wg[idx]);
    }
    if (tid < 64) biasS[tid] = bg[tid];
}

// ===========================================================================
// Merged projection kernel, grid=288: path0 = x-chain (fp32 x1 + tc x2/q/v),
// path1 = event chain (gather + tc ef0/ef1/k). 2 CTAs/SM co-resident.
// smem map: [0,9216) A bf16 | [9216,18432) B bf16 | fp32 phase: S0@0 S1@17408
//           Wt/W16@34816 | bias@44032. Total 51456 B.
// ===========================================================================
#define AOFF 0
#define BOFF 9216
#define WOFF 34816
#define BIASOFF 44032
#define P2_SMEM 51456

__global__ __launch_bounds__(256, 2)
void proj2_kernel(const float* __restrict__ x, const float* __restrict__ event,
                  const float* __restrict__ Wx0, const float* __restrict__ bx0,
                  const float* __restrict__ Wx1, const float* __restrict__ bx1,
                  const float* __restrict__ We0, const float* __restrict__ be0,
                  const float* __restrict__ We1, const float* __restrict__ be1,
                  const float* __restrict__ Wq,  const float* __restrict__ bq,
                  const float* __restrict__ Wk,  const float* __restrict__ bk,
                  const float* __restrict__ Wv,  const float* __restrict__ bv)
{
    extern __shared__ char smc[];
    const uint32_t sb = smem_u32(smc);
    const int tid = threadIdx.x;
    const int lane = tid & 31, w = tid >> 5;
    const int w4 = w & 3, h = w >> 2;
    const int path = blockIdx.x / 144;
    const int id   = blockIdx.x % 144;
    const int b = id / 36, n0 = (id % 36) * 64;
    float* biasS = (float*)(smc + BIASOFF);

    if (path == 0) {
        // ---------- phase A: x1 fp32 (residual accuracy) ----------
        float* S0 = (float*)smc;
        float* S1 = (float*)(smc + 17408);
        float* Wt = (float*)(smc + WOFF);
        const float* xb = x + b * 64 * NPOS + n0;
#pragma unroll
        for (int idx = tid; idx < 4096; idx += 256) {
            int c = idx >> 6, j = idx & 63;
            S0[c * SP + j] = xb[c * NPOS + j];
        }
        loadWt(Wx0, Wt, tid);
        __syncthreads();
        gemm64_relu(S0, Wt, bx0, S1, tid & 15, tid >> 4);
        __syncthreads();

        float* x1g = g_x1 + b * 64 * NPOS + n0;
#pragma unroll
        for (int idx = tid; idx < 4096; idx += 256) {
            int c = idx >> 6, j = idx & 63;
            x1g[c * NPOS + j] = S1[c * SP + j];
        }
        // x1 -> A bf16 [pos][chan] (A region doesn't overlap S1)
#pragma unroll
        for (int idx = tid; idx < 4096; idx += 256) {
            int j = idx & 63, o = idx >> 6;
            *(__nv_bfloat16*)(smc + AOFF + j * 144 + o * 2) = __float2bfloat16(S1[o * SP + j]);
        }
        loadW16(Wx1, bx1, smc, WOFF, biasS, tid);   // Wt region dead
        __syncthreads();

        // ---------- phase B: tensor chain ----------
        gemm_tc(sb, smc, AOFF, WOFF, biasS, BOFF, lane, w4, h);   // x2 -> B
        __syncthreads();
        loadW16(Wq, bq, smc, WOFF, biasS, tid);
        __syncthreads();
        gemm_tc(sb, smc, BOFF, WOFF, biasS, AOFF, lane, w4, h);   // q -> A
        __syncthreads();
        {   // store q (B,N,C) + load Wv
            char* qg = (char*)(g_qb + (size_t)(b * NPOS + n0) * 64);
#pragma unroll
            for (int it = 0; it < 2; ++it) {
                int idx = tid + it * 256;
                int p = idx >> 3, c16 = (idx & 7) * 16;
                *(uint4*)(qg + p * 128 + c16) = *(const uint4*)(smc + AOFF + p * 144 + c16);
            }
            loadW16(Wv, bv, smc, WOFF, biasS, tid);
        }
        __syncthreads();
        gemm_tc(sb, smc, BOFF, WOFF, biasS, AOFF, lane, w4, h);   // v -> A
        __syncthreads();
        {   // store v transposed to (B,C,N)
            char* vbg = (char*)(g_vb + (size_t)b * 64 * NPOS + n0);
#pragma unroll
            for (int idx = tid; idx < 2048; idx += 256) {
                int c = idx >> 5, p2 = (idx & 31) * 2;
                uint32_t lo = *(const uint16_t*)(smc + AOFF + p2 * 144 + c * 2);
                uint32_t hi = *(const uint16_t*)(smc + AOFF + (p2 + 1) * 144 + c * 2);
                *(uint32_t*)(vbg + (size_t)c * (NPOS * 2) + p2 * 2) = lo | (hi << 16);
            }
        }
    } else {
        // ---------- event chain: subsample gather -> bf16 A ----------
        const float* eb = event + (long)b * 64 * 768 * 768;
#pragma unroll
        for (int idx = tid; idx < 4096; idx += 256) {
            int j = idx & 63, c = idx >> 6;
            int n = n0 + j;
            int hh = n / 48;
            int ww = n - hh * 48;
            float v = eb[((long)c * 768 + hh * 16) * 768 + ww * 16];
            *(__nv_bfloat16*)(smc + AOFF + j * 144 + c * 2) = __float2bfloat16(v);
        }
        loadW16(We0, be0, smc, WOFF, biasS, tid);
        __syncthreads();
        gemm_tc(sb, smc, AOFF, WOFF, biasS, BOFF, lane, w4, h);   // ef0 -> B
        __syncthreads();
        loadW16(We1, be1, smc, WOFF, biasS, tid);
        __syncthreads();
        gemm_tc(sb, smc, BOFF, WOFF, biasS, AOFF, lane, w4, h);   // ef1 -> A
        __syncthreads();
        loadW16(Wk, bk, smc, WOFF, biasS, tid);
        __syncthreads();
        gemm_tc(sb, smc, AOFF, WOFF, biasS, BOFF, lane, w4, h);   // k -> B
        __syncthreads();
        {   // store k (B,N,C)
            char* kgd = (char*)(g_kb + (size_t)(b * NPOS + n0) * 64);
#pragma unroll
            for (int it = 0; it < 2; ++it) {
                int idx = tid + it * 256;
                int p = idx >> 3, c16 = (idx & 7) * 16;
                *(uint4*)(kgd + p * 128 + c16) = *(const uint4*)(smc + BOFF + p * 144 + c16);
            }
        }
    }
}

// ===========================================================================
// mma.sync attention (unchanged from R7): grid=288, split-K halves,
// 3-stage cp.async pipeline, 2 CTAs/SM, raw partials to global.
// ===========================================================================
#define TSTRIDE 144
#define SM_Q   0
#define SM_K   9216
#define SM_V   36864
#define SM_O   9216
#define SM_L   26624
#define ATTN_SMEM 64512
#define KITERS 18

__global__ __launch_bounds__(256, 2)
void attn_mma_kernel()
{
    extern __shared__ char smc[];
    const uint32_t sb = smem_u32(smc);
    const int tid = threadIdx.x;
    const int lane = tid & 31, w = tid >> 5;
    const int w4 = w & 3, h = w >> 2;
    const int b   = blockIdx.x / 72;
    const int rem = blockIdx.x % 72;
    const int m0  = (rem >> 1) * 64;
    const int kh  = rem & 1;
    const int nbase = kh * 1152;

    const char* qg = (const char*)(g_qb + (size_t)(b * NPOS + m0) * 64);
    const char* kg = (const char*)(g_kb + (size_t)(b * NPOS + nbase) * 64);
    const char* vg = (const char*)(g_vb + (size_t)b * 64 * NPOS) + nbase * 2;

    const int row0 = tid >> 3,         c16_0 = (tid & 7) * 16;
    const int row1 = (tid + 256) >> 3, c16_1 = (tid & 7) * 16;

    CP16(sb + SM_Q + row0 * TSTRIDE + c16_0, qg + row0 * 128 + c16_0);
    CP16(sb + SM_Q + row1 * TSTRIDE + c16_1, qg + row1 * 128 + c16_1);
    CP16(sb + SM_K + row0 * TSTRIDE + c16_0, kg + row0 * 128 + c16_0);
    CP16(sb + SM_K + row1 * TSTRIDE + c16_1, kg + row1 * 128 + c16_1);
    CP16(sb + SM_V + row0 * TSTRIDE + c16_0, vg + (size_t)row0 * (NPOS * 2) + c16_0);
    CP16(sb + SM_V + row1 * TSTRIDE + c16_1, vg + (size_t)row1 * (NPOS * 2) + c16_1);
    CP_COMMIT();
    {
        const char* kgs = kg + (size_t)64 * 128;
        CP16(sb + SM_K + 9216 + row0 * TSTRIDE + c16_0, kgs + row0 * 128 + c16_0);
        CP16(sb + SM_K + 9216 + row1 * TSTRIDE + c16_1, kgs + row1 * 128 + c16_1);
        CP16(sb + SM_V + 9216 + row0 * TSTRIDE + c16_0, vg + (size_t)row0 * (NPOS * 2) + 128 + c16_0);
        CP16(sb + SM_V + 9216 + row1 * TSTRIDE + c16_1, vg + (size_t)row1 * (NPOS * 2) + 128 + c16_1);
    }
    CP_COMMIT();
    CP_WAIT1();
    __syncthreads();

    uint32_t qf[4][4];
    {
        uint32_t base = sb + SM_Q + (w4 * 16 + (lane & 15)) * TSTRIDE + ((lane >> 4) << 4);
#pragma unroll
        for (int ks = 0; ks < 4; ++ks) ldsm4(qf[ks], base + ks * 32);
    }

    float O[8][4];
#pragma unroll
    for (int j = 0; j < 8; ++j)
#pragma unroll
        for (int e = 0; e < 4; ++e) O[j][e] = 0.f;
    float lsum0 = 0.f, lsum1 = 0.f;

    const int bro = ((lane & 16) >> 1) + (lane & 7);
    const int bco = (lane & 8) * 2;

    int cur = 0, nxt2 = 2;

    for (int i = 0; i < KITERS; ++i) {
        if (i + 2 < KITERS) {
            const int n2 = (i + 2) * 64;
            const char* kgs = kg + (size_t)n2 * 128;
            const uint32_t ko = sb + SM_K + nxt2 * 9216;
            const uint32_t vo = sb + SM_V + nxt2 * 9216;
            CP16(ko + row0 * TSTRIDE + c16_0, kgs + row0 * 128 + c16_0);
            CP16(ko + row1 * TSTRIDE + c16_1, kgs + row1 * 128 + c16_1);
            CP16(vo + row0 * TSTRIDE + c16_0, vg + (size_t)row0 * (NPOS * 2) + n2 * 2 + c16_0);
            CP16(vo + row1 * TSTRIDE + c16_1, vg + (size_t)row1 * (NPOS * 2) + n2 * 2 + c16_1);
        }
        CP_COMMIT();

        const uint32_t kbase = sb + SM_K + cur * 9216;
        const uint32_t vbase = sb + SM_V + cur * 9216;

        float S[4][4];
#pragma unroll
        for (int j = 0; j < 4; ++j)
#pragma unroll
            for (int e = 0; e < 4; ++e) S[j][e] = 0.f;
#pragma unroll
        for (int ks = 0; ks < 4; ++ks) {
#pragma unroll
            for (int p = 0; p < 2; ++p) {
                uint32_t kb[4];
                ldsm4(kb, kbase + (h * 32 + 16 * p + bro) * TSTRIDE + ks * 32 + bco);
                mma16816(S[2 * p],     qf[ks], kb[0], kb[1]);
                mma16816(S[2 * p + 1], qf[ks], kb[2], kb[3]);
            }
        }

        uint32_t P[2][4];
#pragma unroll
        for (int j = 0; j < 4; ++j) {
            float e0 = __expf(S[j][0] - EXP_SHIFT);
            float e1 = __expf(S[j][1] - EXP_SHIFT);
            float e2 = __expf(S[j][2] - EXP_SHIFT);
            float e3 = __expf(S[j][3] - EXP_SHIFT);
            lsum0 += e0 + e1;
            lsum1 += e2 + e3;
            P[j >> 1][(j & 1) * 2 + 0] = pack_bf16x2(e0, e1);
            P[j >> 1][(j & 1) * 2 + 1] = pack_bf16x2(e2, e3);
        }

#pragma unroll
        for (int step = 0; step < 2; ++step) {
#pragma unroll
            for (int p = 0; p < 4; ++p) {
                uint32_t vb[4];
                ldsm4(vb, vbase + (16 * p + bro) * TSTRIDE + h * 64 + step * 32 + bco);
                mma16816(O[2 * p],     P[step], vb[0], vb[1]);
                mma16816(O[2 * p + 1], P[step], vb[2], vb[3]);
            }
        }

        CP_WAIT1();
        __syncthreads();

        cur = (cur == 2) ? 0 : cur + 1;
        nxt2 = (nxt2 == 2) ? 0 : nxt2 + 1;
    }

    lsum0 += __shfl_xor_sync(0xffffffffu, lsum0, 1);
    lsum0 += __shfl_xor_sync(0xffffffffu, lsum0, 2);
    lsum1 += __shfl_xor_sync(0xffffffffu, lsum1, 1);
    lsum1 += __shfl_xor_sync(0xffffffffu, lsum1, 2);

    float* so  = (float*)(smc + SM_O);
    float* lar = (float*)(smc + SM_L);
    const int g = lane >> 2, t2 = (lane & 3) * 2;
    const int m_lo = w4 * 16 + g, m_hi = m_lo + 8;

    if (h == 0) {
#pragma unroll
        for (int j = 0; j < 8; ++j) {
            int c = 8 * j + t2;
            so[c * 68 + m_lo]       = O[j][0];
            so[(c + 1) * 68 + m_lo] = O[j][1];
            so[c * 68 + m_hi]       = O[j][2];
            so[(c + 1) * 68 + m_hi] = O[j][3];
        }
        if ((lane & 3) == 0) { lar[m_lo] = lsum0; lar[m_hi] = lsum1; }
    }
    __syncthreads();
    if (h == 1) {
#pragma unroll
        for (int j = 0; j < 8; ++j) {
            int c = 8 * j + t2;
            so[c * 68 + m_lo]       += O[j][0];
            so[(c + 1) * 68 + m_lo] += O[j][1];
            so[c * 68 + m_hi]       += O[j][2];
            so[(c + 1) * 68 + m_hi] += O[j][3];
        }
        if ((lane & 3) == 0) { lar[m_lo] += lsum0; lar[m_hi] += lsum1; }
    }
    __syncthreads();

    float* pb = g_part + (size_t)blockIdx.x * 4096;
#pragma unroll
    for (int it = 0; it < 4; ++it) {
        int idx = tid + it * 256;
        int c = idx >> 4, m4 = (idx & 15) * 4;
        *(float4*)(pb + c * 64 + m4) = *(const float4*)(so + c * 68 + m4);
    }
    if (tid < 64) g_lpart[blockIdx.x * 64 + tid] = lar[tid];
}

// ===========================================================================
// Combine kernel (unchanged)
// ===========================================================================
__global__ __launch_bounds__(256, 4)
void combine_kernel(const float* __restrict__ gamma, float* __restrict__ out)
{
    __shared__ float linv[64];
    const int tid = threadIdx.x;
    const int b = blockIdx.x / 36;
    const int m0 = (blockIdx.x % 36) * 64;
    const int pair = blockIdx.x * 2;

    if (tid < 64) {
        float l = g_lpart[pair * 64 + tid] + g_lpart[(pair + 1) * 64 + tid];
        linv[tid] = (THITA * gamma[0]) / l;
    }
    __syncthreads();

    const float* p0 = g_part + (size_t)pair * 4096;
    const float* p1 = p0 + 4096;
    const float* x1b = g_x1 + (size_t)b * 64 * NPOS + m0;
    float* ob = out + (size_t)b * 64 * NPOS + m0;

#pragma unroll
    for (int it = 0; it < 4; ++it) {
        int idx = tid + it * 256;
        int c = idx >> 4, m4 = (idx & 15) * 4;
        float4 a4 = *(const float4*)(p0 + c * 64 + m4);
        float4 b4 = *(const float4*)(p1 + c * 64 + m4);
        float4 l4 = *(const float4*)(linv + m4);
        float4 xv = *(const float4*)(x1b + (size_t)c * NPOS + m4);
        float4 r;
        r.x = (a4.x + b4.x) * l4.x + xv.x;
        r.y = (a4.y + b4.y) * l4.y + xv.y;
        r.z = (a4.z + b4.z) * l4.z + xv.z;
        r.w = (a4.w + b4.w) * l4.w + xv.w;
        *(float4*)(ob + (size_t)c * NPOS + m4) = r;
    }
}

// ===========================================================================
extern "C" void kernel_launch(void* const* d_in, const int* in_sizes, int n_in,
                              void* d_out, int out_size)
{
    const float* x     = (const float*)d_in[0];
    const float* event = (const float*)d_in[1];
    const float* Wx0 = (const float*)d_in[2];
    const float* bx0 = (const float*)d_in[3];
    const float* Wx1 = (const float*)d_in[4];
    const float* bx1 = (const float*)d_in[5];
    const float* We0 = (const float*)d_in[6];
    const float* be0 = (const float*)d_in[7];
    const float* We1 = (const float*)d_in[8];
    const float* be1 = (const float*)d_in[9];
    const float* Wq  = (const float*)d_in[10];
    const float* bq  = (const float*)d_in[11];
    const float* Wk  = (const float*)d_in[12];
    const float* bk  = (const float*)d_in[13];
    const float* Wv  = (const float*)d_in[14];
    const float* bv  = (const float*)d_in[15];
    const float* gamma = (const float*)d_in[16];
    float* out = (float*)d_out;

    cudaFuncSetAttribute(proj2_kernel, cudaFuncAttributeMaxDynamicSharedMemorySize, P2_SMEM);
    cudaFuncSetAttribute(attn_mma_kernel, cudaFuncAttributeMaxDynamicSharedMemorySize, ATTN_SMEM);

    proj2_kernel<<<288, 256, P2_SMEM>>>(x, event,
                                        Wx0, bx0, Wx1, bx1,
                                        We0, be0, We1, be1,
                                        Wq, bq, Wk, bk, Wv, bv);
    attn_mma_kernel<<<288, 256, ATTN_SMEM>>>();
    combine_kernel<<<144, 256>>>(gamma, out);
}